// round 1
// baseline (speedup 1.0000x reference)
#include <cuda_runtime.h>
#include <cuda_bf16.h>

#define N_NODES 100000
#define N_EDGES 1600000
#define HID 64
#define FEAT 128
#define NB 64
#define EPS 1e-5f

// ---------------- scratch (static device globals; no allocs) ----------------
__device__ float    g_deg[N_NODES];
__device__ float    g_norm[N_EDGES];
__device__ float    g_h1[N_NODES * HID];
__device__ float    g_acc1[N_NODES * HID];
__device__ float    g_h2[N_NODES * HID];
__device__ float    g_acc2[N_NODES * HID];
__device__ float    g_sum[4 * HID];      // [sum1, sq1, sum2, sq2]
__device__ unsigned g_gx[NB * HID];      // segment-max (float bits, all >= 0)

// ---------------- init: deg=1 (self loop), zero stats, zero gx --------------
__global__ void init_kernel() {
    int i = blockIdx.x * 256 + threadIdx.x;
    if (i < N_NODES) g_deg[i] = 1.0f;
    if (i < 4 * HID) g_sum[i] = 0.0f;
    if (i < NB * HID) g_gx[i] = 0u;
}

// ---------------- degree: deg[c] += w -----------------------------
__global__ void deg_kernel(const int* __restrict__ col, const float* __restrict__ w) {
    int e = blockIdx.x * 256 + threadIdx.x;
    if (e < N_EDGES) atomicAdd(&g_deg[col[e]], w[e]);
}

// ---------------- edge norm: w / sqrt(deg[r]*deg[c]) ----------------------
__global__ void norm_kernel(const int* __restrict__ row, const int* __restrict__ col,
                            const float* __restrict__ w) {
    int e = blockIdx.x * 256 + threadIdx.x;
    if (e < N_EDGES)
        g_norm[e] = w[e] * rsqrtf(g_deg[row[e]] * g_deg[col[e]]);
}

// ---------------- gemm1: h1 = x @ W1 ; acc1 = h1 / deg (self-loop) ----------
// 256 thr, 32 rows/block, each thread: 1 row x 8 cols
__global__ void gemm1_kernel(const float* __restrict__ x, const float* __restrict__ W) {
    __shared__ float Ws[FEAT * HID];   // 32 KB
    __shared__ float Xs[32 * FEAT];    // 16 KB
    int tid = threadIdx.x;
    const float4* W4 = (const float4*)W;
    float4* Ws4 = (float4*)Ws;
    #pragma unroll
    for (int i = 0; i < 8; i++) Ws4[tid + i * 256] = W4[tid + i * 256];
    const float4* X4 = (const float4*)(x + (size_t)blockIdx.x * 32 * FEAT);
    float4* Xs4 = (float4*)Xs;
    #pragma unroll
    for (int i = 0; i < 4; i++) Xs4[tid + i * 256] = X4[tid + i * 256];
    __syncthreads();

    int row = tid >> 3;
    int jb  = (tid & 7) << 3;
    float acc[8] = {0,0,0,0,0,0,0,0};
    const float* xr = &Xs[row * FEAT];
    #pragma unroll 8
    for (int k = 0; k < FEAT; k++) {
        float xv = xr[k];
        float4 w0 = *(const float4*)&Ws[k * HID + jb];
        float4 w1 = *(const float4*)&Ws[k * HID + jb + 4];
        acc[0] += xv * w0.x; acc[1] += xv * w0.y; acc[2] += xv * w0.z; acc[3] += xv * w0.w;
        acc[4] += xv * w1.x; acc[5] += xv * w1.y; acc[6] += xv * w1.z; acc[7] += xv * w1.w;
    }
    int gr = blockIdx.x * 32 + row;
    float d2 = 1.0f / g_deg[gr];  // dis^2 for self loop
    float4 h0 = {acc[0], acc[1], acc[2], acc[3]};
    float4 h1 = {acc[4], acc[5], acc[6], acc[7]};
    *(float4*)&g_h1[gr * HID + jb]     = h0;
    *(float4*)&g_h1[gr * HID + jb + 4] = h1;
    float4 a0 = {acc[0]*d2, acc[1]*d2, acc[2]*d2, acc[3]*d2};
    float4 a1 = {acc[4]*d2, acc[5]*d2, acc[6]*d2, acc[7]*d2};
    *(float4*)&g_acc1[gr * HID + jb]     = a0;
    *(float4*)&g_acc1[gr * HID + jb + 4] = a1;
}

// ---------------- gemm2: h2 = h1act @ W2 ; acc2 = h2 / deg ------------------
__global__ void gemm2_kernel(const float* __restrict__ W) {
    __shared__ float Ws[HID * HID];    // 16 KB
    __shared__ float Xs[32 * HID];     // 8 KB
    int tid = threadIdx.x;
    const float4* W4 = (const float4*)W;
    float4* Ws4 = (float4*)Ws;
    #pragma unroll
    for (int i = 0; i < 4; i++) Ws4[tid + i * 256] = W4[tid + i * 256];
    const float4* X4 = (const float4*)(g_h1 + (size_t)blockIdx.x * 32 * HID);
    float4* Xs4 = (float4*)Xs;
    #pragma unroll
    for (int i = 0; i < 2; i++) Xs4[tid + i * 256] = X4[tid + i * 256];
    __syncthreads();

    int row = tid >> 3;
    int jb  = (tid & 7) << 3;
    float acc[8] = {0,0,0,0,0,0,0,0};
    const float* xr = &Xs[row * HID];
    #pragma unroll 8
    for (int k = 0; k < HID; k++) {
        float xv = xr[k];
        float4 w0 = *(const float4*)&Ws[k * HID + jb];
        float4 w1 = *(const float4*)&Ws[k * HID + jb + 4];
        acc[0] += xv * w0.x; acc[1] += xv * w0.y; acc[2] += xv * w0.z; acc[3] += xv * w0.w;
        acc[4] += xv * w1.x; acc[5] += xv * w1.y; acc[6] += xv * w1.z; acc[7] += xv * w1.w;
    }
    int gr = blockIdx.x * 32 + row;
    float d2 = 1.0f / g_deg[gr];
    float4 h0 = {acc[0], acc[1], acc[2], acc[3]};
    float4 h1 = {acc[4], acc[5], acc[6], acc[7]};
    *(float4*)&g_h2[gr * HID + jb]     = h0;
    *(float4*)&g_h2[gr * HID + jb + 4] = h1;
    float4 a0 = {acc[0]*d2, acc[1]*d2, acc[2]*d2, acc[3]*d2};
    float4 a1 = {acc[4]*d2, acc[5]*d2, acc[6]*d2, acc[7]*d2};
    *(float4*)&g_acc2[gr * HID + jb]     = a0;
    *(float4*)&g_acc2[gr * HID + jb + 4] = a1;
}

// ---------------- scatter: acc[c] += h[r] * norm[e]  (16 thr / edge) --------
__global__ void scatter_kernel(const int* __restrict__ row, const int* __restrict__ col,
                               int layer) {
    long long gid = (long long)blockIdx.x * 256 + threadIdx.x;
    int e = (int)(gid >> 4);
    int p = (int)(gid & 15);
    if (e >= N_EDGES) return;
    const float* h = layer ? g_h2 : g_h1;
    float* acc     = layer ? g_acc2 : g_acc1;
    int r = row[e], c = col[e];
    float nm = g_norm[e];
    float4 hv = *(const float4*)(h + (size_t)r * HID + p * 4);
    float* dst = acc + (size_t)c * HID + p * 4;
    asm volatile("red.global.add.v4.f32 [%0], {%1,%2,%3,%4};"
                 :: "l"(dst), "f"(hv.x * nm), "f"(hv.y * nm), "f"(hv.z * nm), "f"(hv.w * nm)
                 : "memory");
}

// ---------------- BN stats: per-column sum & sumsq --------------------------
// 256 thr = 4 row-groups x 64 cols, 512 rows per block
__global__ void stats_kernel(int layer) {
    const float* acc = layer ? g_acc2 : g_acc1;
    float* sum = g_sum + layer * 2 * HID;
    float* sq  = sum + HID;
    int j = threadIdx.x & 63;
    int g = threadIdx.x >> 6;
    int rend = min(blockIdx.x * 512 + 512, N_NODES);
    float s = 0.f, q = 0.f;
    for (int r = blockIdx.x * 512 + g; r < rend; r += 4) {
        float v = acc[(size_t)r * HID + j];
        s += v; q += v * v;
    }
    __shared__ float ss[4][HID], qq[4][HID];
    ss[g][j] = s; qq[g][j] = q;
    __syncthreads();
    if (g == 0) {
        s = ss[0][j] + ss[1][j] + ss[2][j] + ss[3][j];
        q = qq[0][j] + qq[1][j] + qq[2][j] + qq[3][j];
        atomicAdd(&sum[j], s);
        atomicAdd(&sq[j], q);
    }
}

// ---------------- BN+ReLU layer1 -> overwrite g_h1 (input of gemm2) ---------
__global__ void bnrelu1_kernel(const float* __restrict__ gamma, const float* __restrict__ beta) {
    int idx = blockIdx.x * 256 + threadIdx.x;
    if (idx >= N_NODES * HID) return;
    int j = idx & 63;
    float m   = g_sum[j] * (1.0f / N_NODES);
    float var = g_sum[HID + j] * (1.0f / N_NODES) - m * m;
    float inv = rsqrtf(var + EPS);
    float v = (g_acc1[idx] - m) * inv * gamma[j] + beta[j];
    g_h1[idx] = fmaxf(v, 0.0f);
}

// ---------------- BN+ReLU layer2 fused with segment-max ---------------------
// 256 thr = 4 row-groups x 64 cols; each thread walks 8 consecutive rows
__global__ void bnrelu2max_kernel(const int* __restrict__ batch,
                                  const float* __restrict__ gamma,
                                  const float* __restrict__ beta) {
    int j = threadIdx.x & 63;
    int g = threadIdx.x >> 6;
    int rbase = (blockIdx.x * 4 + g) * 8;
    if (rbase >= N_NODES) return;
    float m   = g_sum[2 * HID + j] * (1.0f / N_NODES);
    float var = g_sum[3 * HID + j] * (1.0f / N_NODES) - m * m;
    float inv = rsqrtf(var + EPS);
    float gj = gamma[j], bj = beta[j];
    int cur = -1;
    float mx = 0.f;
    #pragma unroll
    for (int k = 0; k < 8; k++) {
        int r = rbase + k;
        if (r >= N_NODES) break;
        int b = batch[r];
        float v = fmaxf((g_acc2[(size_t)r * HID + j] - m) * inv * gj + bj, 0.f);
        if (b != cur) {
            if (cur >= 0 && mx > 0.f) atomicMax(&g_gx[cur * HID + j], __float_as_uint(mx));
            cur = b; mx = v;
        } else {
            mx = fmaxf(mx, v);
        }
    }
    if (cur >= 0 && mx > 0.f) atomicMax(&g_gx[cur * HID + j], __float_as_uint(mx));
}

// ---------------- head: speed enc + route enc + MLP (one block, 64 thr) -----
__global__ void head_kernel(const float* __restrict__ speed, const float* __restrict__ route,
                            const float* __restrict__ sw, const float* __restrict__ sb,
                            const float* __restrict__ sg, const float* __restrict__ sbe,
                            const float* __restrict__ cw, const float* __restrict__ cb,
                            const float* __restrict__ rg, const float* __restrict__ rbe,
                            const float* __restrict__ rw, const float* __restrict__ rb,
                            const float* __restrict__ ow1, const float* __restrict__ ob1,
                            const float* __restrict__ og, const float* __restrict__ obe,
                            const float* __restrict__ ow2, const float* __restrict__ ob2,
                            float* __restrict__ out) {
    int b = threadIdx.x;  // 64 threads
    __shared__ float s_v[NB][4];
    __shared__ float s_rc[NB][10];
    __shared__ float s_o1[NB][16];
    __shared__ float s_m[16], s_i[16];

    // speed: [B,1] @ [1,4]
    float sp = speed[b];
    #pragma unroll
    for (int j = 0; j < 4; j++) s_v[b][j] = sp * sw[j] + sb[j];

    // route conv1d(2->1, k=3, SAME): route layout [b][t][i]
    const float* rt = route + b * 20;
    #pragma unroll
    for (int t = 0; t < 10; t++) {
        float a = cb[0];
        #pragma unroll
        for (int k = 0; k < 3; k++) {
            int tau = t + k - 1;
            if (tau >= 0 && tau < 10) {
                a += rt[tau * 2 + 0] * cw[k];
                a += rt[tau * 2 + 1] * cw[3 + k];
            }
        }
        s_rc[b][t] = a;
    }
    __syncthreads();

    // BN stats: speed cols (threads 0..3), route-all (thread 8)
    if (b < 4) {
        float s = 0.f, q = 0.f;
        for (int i = 0; i < NB; i++) { float v = s_v[i][b]; s += v; q += v * v; }
        float m = s / NB, var = q / NB - m * m;
        s_m[b] = m; s_i[b] = rsqrtf(var + EPS);
    }
    if (b == 8) {
        float s = 0.f, q = 0.f;
        for (int i = 0; i < NB; i++)
            for (int t = 0; t < 10; t++) { float v = s_rc[i][t]; s += v; q += v * v; }
        float m = s / 640.f, var = q / 640.f - m * m;
        s_m[8] = m; s_i[8] = rsqrtf(var + EPS);
    }
    __syncthreads();

    float vj[4];
    #pragma unroll
    for (int j = 0; j < 4; j++)
        vj[j] = fmaxf((s_v[b][j] - s_m[j]) * s_i[j] * sg[j] + sbe[j], 0.f);

    float rcn[10];
    #pragma unroll
    for (int t = 0; t < 10; t++)
        rcn[t] = fmaxf((s_rc[b][t] - s_m[8]) * s_i[8] * rg[0] + rbe[0], 0.f);

    float rj[4];
    #pragma unroll
    for (int j = 0; j < 4; j++) {
        float a = rb[j];
        #pragma unroll
        for (int t = 0; t < 10; t++) a += rcn[t] * rw[t * 4 + j];
        rj[j] = a;
    }

    // o1 = cat([gx, v, r]) @ ow1 + ob1, cat dim = 72
    #pragma unroll
    for (int j = 0; j < 16; j++) {
        float a = ob1[j];
        for (int k = 0; k < HID; k++)
            a += __uint_as_float(g_gx[b * HID + k]) * ow1[k * 16 + j];
        #pragma unroll
        for (int k = 0; k < 4; k++) a += vj[k] * ow1[(HID + k) * 16 + j];
        #pragma unroll
        for (int k = 0; k < 4; k++) a += rj[k] * ow1[(HID + 4 + k) * 16 + j];
        s_o1[b][j] = a;
    }
    __syncthreads();
    if (b < 16) {
        float s = 0.f, q = 0.f;
        for (int i = 0; i < NB; i++) { float v = s_o1[i][b]; s += v; q += v * v; }
        float m = s / NB, var = q / NB - m * m;
        s_m[b] = m; s_i[b] = rsqrtf(var + EPS);
    }
    __syncthreads();
    float on[16];
    #pragma unroll
    for (int j = 0; j < 16; j++)
        on[j] = fmaxf((s_o1[b][j] - s_m[j]) * s_i[j] * og[j] + obe[j], 0.f);
    #pragma unroll
    for (int a = 0; a < 5; a++) {
        float o = ob2[a];
        #pragma unroll
        for (int j = 0; j < 16; j++) o += on[j] * ow2[j * 5 + a];
        out[b * 5 + a] = o;
    }
}

// ---------------------------------------------------------------------------
extern "C" void kernel_launch(void* const* d_in, const int* in_sizes, int n_in,
                              void* d_out, int out_size) {
    const float* x    = (const float*)d_in[0];
    const int*   ei   = (const int*)d_in[1];
    const float* ew   = (const float*)d_in[2];
    const int*   bidx = (const int*)d_in[3];
    const float* speed = (const float*)d_in[4];
    const float* route = (const float*)d_in[5];
    const float* W1 = (const float*)d_in[6];
    const float* g1 = (const float*)d_in[8];
    const float* be1 = (const float*)d_in[9];
    const float* W2 = (const float*)d_in[10];
    const float* g2 = (const float*)d_in[12];
    const float* be2 = (const float*)d_in[13];
    const float* sw  = (const float*)d_in[14];
    const float* sb  = (const float*)d_in[15];
    const float* sg  = (const float*)d_in[16];
    const float* sbe = (const float*)d_in[17];
    const float* cw  = (const float*)d_in[18];
    const float* cb  = (const float*)d_in[19];
    const float* rg  = (const float*)d_in[20];
    const float* rbe = (const float*)d_in[21];
    const float* rw  = (const float*)d_in[22];
    const float* rb  = (const float*)d_in[23];
    const float* ow1 = (const float*)d_in[24];
    const float* ob1 = (const float*)d_in[25];
    const float* og  = (const float*)d_in[26];
    const float* obe = (const float*)d_in[27];
    const float* ow2 = (const float*)d_in[28];
    const float* ob2 = (const float*)d_in[29];
    float* out = (float*)d_out;

    const int* row = ei;            // edge_index[0]
    const int* col = ei + N_EDGES;  // edge_index[1]

    init_kernel<<<(N_NODES + 255) / 256, 256>>>();
    deg_kernel<<<(N_EDGES + 255) / 256, 256>>>(col, ew);
    norm_kernel<<<(N_EDGES + 255) / 256, 256>>>(row, col, ew);

    gemm1_kernel<<<N_NODES / 32, 256>>>(x, W1);
    scatter_kernel<<<(N_EDGES * 16) / 256, 256>>>(row, col, 0);
    stats_kernel<<<(N_NODES + 511) / 512, 256>>>(0);
    bnrelu1_kernel<<<(N_NODES * HID + 255) / 256, 256>>>(g1, be1);

    gemm2_kernel<<<N_NODES / 32, 256>>>(W2);
    scatter_kernel<<<(N_EDGES * 16) / 256, 256>>>(row, col, 1);
    stats_kernel<<<(N_NODES + 511) / 512, 256>>>(1);
    bnrelu2max_kernel<<<(N_NODES + 31) / 32, 256>>>(bidx, g2, be2);

    head_kernel<<<1, 64>>>(speed, route, sw, sb, sg, sbe, cw, cb, rg, rbe,
                           rw, rb, ow1, ob1, og, obe, ow2, ob2, out);
}

// round 9
// speedup vs baseline: 1.4329x; 1.4329x over previous
#include <cuda_runtime.h>
#include <cuda_bf16.h>

#define N_NODES 100000
#define N_EDGES 1600000
#define HID 64
#define FEAT 128
#define NB 64
#define EPS 1e-5f

// ---------------- scratch (static device globals; no allocs) ----------------
__device__ float    g_deg[N_NODES];
__device__ float    g_norm[N_EDGES];
__device__ float    g_h1[N_NODES * HID];
__device__ float    g_acc1[N_NODES * HID];
__device__ float    g_h2[N_NODES * HID];
__device__ float    g_acc2[N_NODES * HID];
__device__ float    g_sum[4 * HID];      // [sum1, sq1, sum2, sq2]
__device__ unsigned g_gx[NB * HID];      // segment-max (float bits, all >= 0)

// ---------------- init: deg=1 (self loop), zero stats, zero gx --------------
__global__ void init_kernel() {
    int i = blockIdx.x * 256 + threadIdx.x;
    if (i < N_NODES) g_deg[i] = 1.0f;
    if (i < 4 * HID) g_sum[i] = 0.0f;
    if (i < NB * HID) g_gx[i] = 0u;
}

// ---------------- degree: deg[c] += w ---------------------------------------
__global__ void deg_kernel(const int* __restrict__ col, const float* __restrict__ w) {
    int e = blockIdx.x * 256 + threadIdx.x;
    if (e < N_EDGES) atomicAdd(&g_deg[col[e]], w[e]);
}

// ---------------- edge norm: w / sqrt(deg[r]*deg[c]) ------------------------
__global__ void norm_kernel(const int* __restrict__ row, const int* __restrict__ col,
                            const float* __restrict__ w) {
    int e = blockIdx.x * 256 + threadIdx.x;
    if (e < N_EDGES)
        g_norm[e] = w[e] * rsqrtf(g_deg[row[e]] * g_deg[col[e]]);
}

// ---------------- gemm1: h1 = x @ W1 ; acc1 = h1 / deg ----------------------
// 32 rows x 64 cols per block, 256 thr = 16 rg x 16 cg, K chunked by 64.
// Thread: rows {rg, rg+16}, cols {cg+16j, j<4}.  ~32 regs, 26.1 KB smem.
#define PP 68    // staging pitch (68 mod 32 = 4 -> conflict-free; 16B-aligned)
__global__ void gemm1_kernel(const float* __restrict__ X, const float* __restrict__ W) {
    __shared__ float Xs[32 * PP];   //  8.7 KB
    __shared__ float Wt[64 * PP];   // 17.4 KB (transposed: Wt[col][k])
    const int tid = threadIdx.x;
    const int cg = tid & 15;
    const int rg = tid >> 4;
    const int rbase = blockIdx.x * 32;

    float acc0[4] = {0.f, 0.f, 0.f, 0.f};
    float acc1[4] = {0.f, 0.f, 0.f, 0.f};

    #pragma unroll
    for (int kc = 0; kc < FEAT; kc += 64) {
        // stage X chunk: 32 rows x 64 k = 512 float4, 2 per thread
        #pragma unroll
        for (int s = 0; s < 2; s++) {
            int t = tid + s * 256;
            int r = t >> 4, k4 = t & 15;
            *(float4*)&Xs[r * PP + k4 * 4] =
                *(const float4*)&X[(size_t)(rbase + r) * FEAT + kc + k4 * 4];
        }
        // stage W chunk transposed: Wt[j][k] = W[(kc+k)*HID + j], 4096 scalars
        #pragma unroll
        for (int s = 0; s < 16; s++) {
            int t = tid + s * 256;
            int k = t >> 6, j = t & 63;
            Wt[j * PP + k] = W[(kc + k) * HID + j];
        }
        __syncthreads();

        #pragma unroll 4
        for (int k0 = 0; k0 < 64; k0 += 4) {
            float4 x0 = *(const float4*)&Xs[rg * PP + k0];
            float4 x1 = *(const float4*)&Xs[(rg + 16) * PP + k0];
            #pragma unroll
            for (int j = 0; j < 4; j++) {
                float4 wv = *(const float4*)&Wt[(cg + 16 * j) * PP + k0];
                acc0[j] += x0.x * wv.x; acc0[j] += x0.y * wv.y;
                acc0[j] += x0.z * wv.z; acc0[j] += x0.w * wv.w;
                acc1[j] += x1.x * wv.x; acc1[j] += x1.y * wv.y;
                acc1[j] += x1.z * wv.z; acc1[j] += x1.w * wv.w;
            }
        }
        __syncthreads();
    }

    int r0 = rbase + rg;
    int r1 = rbase + rg + 16;
    float d0 = 1.0f / g_deg[r0];
    float d1 = 1.0f / g_deg[r1];
    #pragma unroll
    for (int j = 0; j < 4; j++) {
        int c = cg + 16 * j;
        g_h1[(size_t)r0 * HID + c] = acc0[j];
        g_acc1[(size_t)r0 * HID + c] = acc0[j] * d0;
        g_h1[(size_t)r1 * HID + c] = acc1[j];
        g_acc1[(size_t)r1 * HID + c] = acc1[j] * d1;
    }
}

// ---------------- gemm2: h2 = h1act @ W2 ; acc2 = h2 / deg ------------------
__global__ void gemm2_kernel(const float* __restrict__ W) {
    __shared__ float Xs[32 * PP];   //  8.7 KB
    __shared__ float Wt[64 * PP];   // 17.4 KB
    const int tid = threadIdx.x;
    const int cg = tid & 15;
    const int rg = tid >> 4;
    const int rbase = blockIdx.x * 32;

    // stage X: 32 rows x 64 k = 512 float4, 2 per thread
    #pragma unroll
    for (int s = 0; s < 2; s++) {
        int t = tid + s * 256;
        int r = t >> 4, k4 = t & 15;
        *(float4*)&Xs[r * PP + k4 * 4] =
            *(const float4*)&g_h1[(size_t)(rbase + r) * HID + k4 * 4];
    }
    // stage W transposed: 4096 scalars, 16 per thread
    #pragma unroll
    for (int s = 0; s < 16; s++) {
        int t = tid + s * 256;
        int k = t >> 6, j = t & 63;
        Wt[j * PP + k] = W[k * HID + j];
    }
    __syncthreads();

    float acc0[4] = {0.f, 0.f, 0.f, 0.f};
    float acc1[4] = {0.f, 0.f, 0.f, 0.f};
    #pragma unroll 4
    for (int k0 = 0; k0 < HID; k0 += 4) {
        float4 x0 = *(const float4*)&Xs[rg * PP + k0];
        float4 x1 = *(const float4*)&Xs[(rg + 16) * PP + k0];
        #pragma unroll
        for (int j = 0; j < 4; j++) {
            float4 wv = *(const float4*)&Wt[(cg + 16 * j) * PP + k0];
            acc0[j] += x0.x * wv.x; acc0[j] += x0.y * wv.y;
            acc0[j] += x0.z * wv.z; acc0[j] += x0.w * wv.w;
            acc1[j] += x1.x * wv.x; acc1[j] += x1.y * wv.y;
            acc1[j] += x1.z * wv.z; acc1[j] += x1.w * wv.w;
        }
    }

    int r0 = rbase + rg;
    int r1 = rbase + rg + 16;
    float d0 = 1.0f / g_deg[r0];
    float d1 = 1.0f / g_deg[r1];
    #pragma unroll
    for (int j = 0; j < 4; j++) {
        int c = cg + 16 * j;
        g_h2[(size_t)r0 * HID + c] = acc0[j];
        g_acc2[(size_t)r0 * HID + c] = acc0[j] * d0;
        g_h2[(size_t)r1 * HID + c] = acc1[j];
        g_acc2[(size_t)r1 * HID + c] = acc1[j] * d1;
    }
}

// ---------------- scatter: acc[c] += h[r] * norm[e]  (16 thr / edge) --------
__global__ void scatter_kernel(const int* __restrict__ row, const int* __restrict__ col,
                               int layer) {
    long long gid = (long long)blockIdx.x * 256 + threadIdx.x;
    int e = (int)(gid >> 4);
    int p = (int)(gid & 15);
    if (e >= N_EDGES) return;
    const float* h = layer ? g_h2 : g_h1;
    float* acc     = layer ? g_acc2 : g_acc1;
    int r = row[e], c = col[e];
    float nm = g_norm[e];
    float4 hv = *(const float4*)(h + (size_t)r * HID + p * 4);
    float* dst = acc + (size_t)c * HID + p * 4;
    asm volatile("red.global.add.v4.f32 [%0], {%1,%2,%3,%4};"
                 :: "l"(dst), "f"(hv.x * nm), "f"(hv.y * nm), "f"(hv.z * nm), "f"(hv.w * nm)
                 : "memory");
}

// ---------------- BN stats: per-column sum & sumsq --------------------------
__global__ void stats_kernel(int layer) {
    const float* acc = layer ? g_acc2 : g_acc1;
    float* sum = g_sum + layer * 2 * HID;
    float* sq  = sum + HID;
    int j = threadIdx.x & 63;
    int g = threadIdx.x >> 6;
    int rend = min(blockIdx.x * 512 + 512, N_NODES);
    float s = 0.f, q = 0.f;
    for (int r = blockIdx.x * 512 + g; r < rend; r += 4) {
        float v = acc[(size_t)r * HID + j];
        s += v; q += v * v;
    }
    __shared__ float ss[4][HID], qq[4][HID];
    ss[g][j] = s; qq[g][j] = q;
    __syncthreads();
    if (g == 0) {
        s = ss[0][j] + ss[1][j] + ss[2][j] + ss[3][j];
        q = qq[0][j] + qq[1][j] + qq[2][j] + qq[3][j];
        atomicAdd(&sum[j], s);
        atomicAdd(&sq[j], q);
    }
}

// ---------------- BN+ReLU layer1 -> overwrite g_h1 (input of gemm2) ---------
__global__ void bnrelu1_kernel(const float* __restrict__ gamma, const float* __restrict__ beta) {
    int idx = blockIdx.x * 256 + threadIdx.x;
    if (idx >= N_NODES * HID) return;
    int j = idx & 63;
    float m   = g_sum[j] * (1.0f / N_NODES);
    float var = g_sum[HID + j] * (1.0f / N_NODES) - m * m;
    float inv = rsqrtf(var + EPS);
    float v = (g_acc1[idx] - m) * inv * gamma[j] + beta[j];
    g_h1[idx] = fmaxf(v, 0.0f);
}

// ---------------- BN+ReLU layer2 fused with segment-max ---------------------
__global__ void bnrelu2max_kernel(const int* __restrict__ batch,
                                  const float* __restrict__ gamma,
                                  const float* __restrict__ beta) {
    int j = threadIdx.x & 63;
    int g = threadIdx.x >> 6;
    int rbase = (blockIdx.x * 4 + g) * 8;
    if (rbase >= N_NODES) return;
    float m   = g_sum[2 * HID + j] * (1.0f / N_NODES);
    float var = g_sum[3 * HID + j] * (1.0f / N_NODES) - m * m;
    float inv = rsqrtf(var + EPS);
    float gj = gamma[j], bj = beta[j];
    int cur = -1;
    float mx = 0.f;
    #pragma unroll
    for (int k = 0; k < 8; k++) {
        int r = rbase + k;
        if (r >= N_NODES) break;
        int b = batch[r];
        float v = fmaxf((g_acc2[(size_t)r * HID + j] - m) * inv * gj + bj, 0.f);
        if (b != cur) {
            if (cur >= 0 && mx > 0.f) atomicMax(&g_gx[cur * HID + j], __float_as_uint(mx));
            cur = b; mx = v;
        } else {
            mx = fmaxf(mx, v);
        }
    }
    if (cur >= 0 && mx > 0.f) atomicMax(&g_gx[cur * HID + j], __float_as_uint(mx));
}

// ---------------- head: speed enc + route enc + MLP (one block, 64 thr) -----
__global__ void head_kernel(const float* __restrict__ speed, const float* __restrict__ route,
                            const float* __restrict__ sw, const float* __restrict__ sb,
                            const float* __restrict__ sg, const float* __restrict__ sbe,
                            const float* __restrict__ cw, const float* __restrict__ cb,
                            const float* __restrict__ rg, const float* __restrict__ rbe,
                            const float* __restrict__ rw, const float* __restrict__ rb,
                            const float* __restrict__ ow1, const float* __restrict__ ob1,
                            const float* __restrict__ og, const float* __restrict__ obe,
                            const float* __restrict__ ow2, const float* __restrict__ ob2,
                            float* __restrict__ out) {
    int b = threadIdx.x;  // 64 threads
    __shared__ float s_v[NB][4];
    __shared__ float s_rc[NB][10];
    __shared__ float s_o1[NB][16];
    __shared__ float s_m[16], s_i[16];

    float sp = speed[b];
    #pragma unroll
    for (int j = 0; j < 4; j++) s_v[b][j] = sp * sw[j] + sb[j];

    const float* rt = route + b * 20;
    #pragma unroll
    for (int t = 0; t < 10; t++) {
        float a = cb[0];
        #pragma unroll
        for (int k = 0; k < 3; k++) {
            int tau = t + k - 1;
            if (tau >= 0 && tau < 10) {
                a += rt[tau * 2 + 0] * cw[k];
                a += rt[tau * 2 + 1] * cw[3 + k];
            }
        }
        s_rc[b][t] = a;
    }
    __syncthreads();

    if (b < 4) {
        float s = 0.f, q = 0.f;
        for (int i = 0; i < NB; i++) { float v = s_v[i][b]; s += v; q += v * v; }
        float m = s / NB, var = q / NB - m * m;
        s_m[b] = m; s_i[b] = rsqrtf(var + EPS);
    }
    if (b == 8) {
        float s = 0.f, q = 0.f;
        for (int i = 0; i < NB; i++)
            for (int t = 0; t < 10; t++) { float v = s_rc[i][t]; s += v; q += v * v; }
        float m = s / 640.f, var = q / 640.f - m * m;
        s_m[8] = m; s_i[8] = rsqrtf(var + EPS);
    }
    __syncthreads();

    float vj[4];
    #pragma unroll
    for (int j = 0; j < 4; j++)
        vj[j] = fmaxf((s_v[b][j] - s_m[j]) * s_i[j] * sg[j] + sbe[j], 0.f);

    float rcn[10];
    #pragma unroll
    for (int t = 0; t < 10; t++)
        rcn[t] = fmaxf((s_rc[b][t] - s_m[8]) * s_i[8] * rg[0] + rbe[0], 0.f);

    float rj[4];
    #pragma unroll
    for (int j = 0; j < 4; j++) {
        float a = rb[j];
        #pragma unroll
        for (int t = 0; t < 10; t++) a += rcn[t] * rw[t * 4 + j];
        rj[j] = a;
    }

    #pragma unroll
    for (int j = 0; j < 16; j++) {
        float a = ob1[j];
        for (int k = 0; k < HID; k++)
            a += __uint_as_float(g_gx[b * HID + k]) * ow1[k * 16 + j];
        #pragma unroll
        for (int k = 0; k < 4; k++) a += vj[k] * ow1[(HID + k) * 16 + j];
        #pragma unroll
        for (int k = 0; k < 4; k++) a += rj[k] * ow1[(HID + 4 + k) * 16 + j];
        s_o1[b][j] = a;
    }
    __syncthreads();
    if (b < 16) {
        float s = 0.f, q = 0.f;
        for (int i = 0; i < NB; i++) { float v = s_o1[i][b]; s += v; q += v * v; }
        float m = s / NB, var = q / NB - m * m;
        s_m[b] = m; s_i[b] = rsqrtf(var + EPS);
    }
    __syncthreads();
    float on[16];
    #pragma unroll
    for (int j = 0; j < 16; j++)
        on[j] = fmaxf((s_o1[b][j] - s_m[j]) * s_i[j] * og[j] + obe[j], 0.f);
    #pragma unroll
    for (int a = 0; a < 5; a++) {
        float o = ob2[a];
        #pragma unroll
        for (int j = 0; j < 16; j++) o += on[j] * ow2[j * 5 + a];
        out[b * 5 + a] = o;
    }
}

// ---------------------------------------------------------------------------
extern "C" void kernel_launch(void* const* d_in, const int* in_sizes, int n_in,
                              void* d_out, int out_size) {
    const float* x    = (const float*)d_in[0];
    const int*   ei   = (const int*)d_in[1];
    const float* ew   = (const float*)d_in[2];
    const int*   bidx = (const int*)d_in[3];
    const float* speed = (const float*)d_in[4];
    const float* route = (const float*)d_in[5];
    const float* W1 = (const float*)d_in[6];
    const float* g1 = (const float*)d_in[8];
    const float* be1 = (const float*)d_in[9];
    const float* W2 = (const float*)d_in[10];
    const float* g2 = (const float*)d_in[12];
    const float* be2 = (const float*)d_in[13];
    const float* sw  = (const float*)d_in[14];
    const float* sb  = (const float*)d_in[15];
    const float* sg  = (const float*)d_in[16];
    const float* sbe = (const float*)d_in[17];
    const float* cw  = (const float*)d_in[18];
    const float* cb  = (const float*)d_in[19];
    const float* rg  = (const float*)d_in[20];
    const float* rbe = (const float*)d_in[21];
    const float* rw  = (const float*)d_in[22];
    const float* rb  = (const float*)d_in[23];
    const float* ow1 = (const float*)d_in[24];
    const float* ob1 = (const float*)d_in[25];
    const float* og  = (const float*)d_in[26];
    const float* obe = (const float*)d_in[27];
    const float* ow2 = (const float*)d_in[28];
    const float* ob2 = (const float*)d_in[29];
    float* out = (float*)d_out;

    const int* row = ei;            // edge_index[0]
    const int* col = ei + N_EDGES;  // edge_index[1]

    init_kernel<<<(N_NODES + 255) / 256, 256>>>();
    deg_kernel<<<(N_EDGES + 255) / 256, 256>>>(col, ew);
    norm_kernel<<<(N_EDGES + 255) / 256, 256>>>(row, col, ew);

    gemm1_kernel<<<N_NODES / 32, 256>>>(x, W1);
    scatter_kernel<<<(N_EDGES * 16) / 256, 256>>>(row, col, 0);
    stats_kernel<<<(N_NODES + 511) / 512, 256>>>(0);
    bnrelu1_kernel<<<(N_NODES * HID + 255) / 256, 256>>>(g1, be1);

    gemm2_kernel<<<N_NODES / 32, 256>>>(W2);
    scatter_kernel<<<(N_EDGES * 16) / 256, 256>>>(row, col, 1);
    stats_kernel<<<(N_NODES + 511) / 512, 256>>>(1);
    bnrelu2max_kernel<<<(N_NODES + 31) / 32, 256>>>(bidx, g2, be2);

    head_kernel<<<1, 64>>>(speed, route, sw, sb, sg, sbe, cw, cb, rg, rbe,
                           rw, rb, ow1, ob1, og, obe, ow2, ob2, out);
}

// round 10
// speedup vs baseline: 1.5941x; 1.1126x over previous
#include <cuda_runtime.h>
#include <cuda_bf16.h>

#define N_NODES 100000
#define N_EDGES 1600000
#define HID 64
#define FEAT 128
#define NB 64
#define EPS 1e-5f
#define NBLK 391   // ceil(N_NODES/256)

// ---------------- scratch (static device globals; no allocs) ----------------
__device__ float    g_deg[N_NODES];
__device__ float    g_norm[N_EDGES];
__device__ float    g_h1[N_NODES * HID];
__device__ float    g_acc1[N_NODES * HID];
__device__ float    g_h2[N_NODES * HID];
__device__ float    g_acc2[N_NODES * HID];
__device__ float    g_sum[4 * HID];      // [sum1, sq1, sum2, sq2]
__device__ unsigned g_gx[NB * HID];      // segment-max (float bits, all >= 0)
// CSR build
__device__ int      g_cnt[N_NODES];
__device__ int      g_start[N_NODES + 1];
__device__ int      g_bsum[512];
__device__ int      g_cursor[N_NODES];
__device__ int      g_er[N_EDGES];       // permuted source row per incoming edge
__device__ float    g_en[N_EDGES];       // permuted norm per incoming edge

// ---------------- init: deg=1, zero stats/gx/cnt/cursor ---------------------
__global__ void init_kernel() {
    int i = blockIdx.x * 256 + threadIdx.x;
    if (i < N_NODES) { g_deg[i] = 1.0f; g_cnt[i] = 0; g_cursor[i] = 0; }
    if (i < 4 * HID) g_sum[i] = 0.0f;
    if (i < NB * HID) g_gx[i] = 0u;
    if (i == 0) g_start[N_NODES] = N_EDGES;
}

// ---------------- degree: deg[c] += w ; hist: cnt[c]++ ----------------------
__global__ void deg_kernel(const int* __restrict__ col, const float* __restrict__ w) {
    int e = blockIdx.x * 256 + threadIdx.x;
    if (e < N_EDGES) {
        int c = col[e];
        atomicAdd(&g_deg[c], w[e]);
        atomicAdd(&g_cnt[c], 1);
    }
}

// ---------------- edge norm: w / sqrt(deg[r]*deg[c]) ------------------------
__global__ void norm_kernel(const int* __restrict__ row, const int* __restrict__ col,
                            const float* __restrict__ w) {
    int e = blockIdx.x * 256 + threadIdx.x;
    if (e < N_EDGES)
        g_norm[e] = w[e] * rsqrtf(g_deg[row[e]] * g_deg[col[e]]);
}

// ---------------- exclusive scan of g_cnt -> g_start (3 kernels) ------------
__global__ void scan1_kernel() {
    __shared__ int sm[256];
    int i = blockIdx.x * 256 + threadIdx.x;
    int v = (i < N_NODES) ? g_cnt[i] : 0;
    sm[threadIdx.x] = v;
    __syncthreads();
    #pragma unroll
    for (int d = 1; d < 256; d <<= 1) {
        int t = (threadIdx.x >= d) ? sm[threadIdx.x - d] : 0;
        __syncthreads();
        sm[threadIdx.x] += t;
        __syncthreads();
    }
    if (i < N_NODES) g_start[i] = sm[threadIdx.x] - v;   // exclusive
    if (threadIdx.x == 255) g_bsum[blockIdx.x] = sm[255];
}
__global__ void scan2_kernel() {
    __shared__ int sm[512];
    int i = threadIdx.x;
    int v = (i < NBLK) ? g_bsum[i] : 0;
    sm[i] = v;
    __syncthreads();
    #pragma unroll
    for (int d = 1; d < 512; d <<= 1) {
        int t = (i >= d) ? sm[i - d] : 0;
        __syncthreads();
        sm[i] += t;
        __syncthreads();
    }
    if (i < NBLK) g_bsum[i] = sm[i] - v;                 // exclusive
}
__global__ void scan3_kernel() {
    int i = blockIdx.x * 256 + threadIdx.x;
    if (i < N_NODES) g_start[i] += g_bsum[blockIdx.x];
}

// ---------------- fill CSR: permute (row, norm) by target -------------------
__global__ void fill_kernel(const int* __restrict__ row, const int* __restrict__ col) {
    int e = blockIdx.x * 256 + threadIdx.x;
    if (e >= N_EDGES) return;
    int c = col[e];
    int p = atomicAdd(&g_cursor[c], 1);
    int i = g_start[c] + p;
    g_er[i] = row[e];
    g_en[i] = g_norm[e];
}

// ---------------- gemm1: h1 = x @ W1 ; acc1 = h1 / deg ----------------------
#define PP 68
__global__ void gemm1_kernel(const float* __restrict__ X, const float* __restrict__ W) {
    __shared__ float Xs[32 * PP];
    __shared__ float Wt[64 * PP];
    const int tid = threadIdx.x;
    const int cg = tid & 15;
    const int rg = tid >> 4;
    const int rbase = blockIdx.x * 32;

    float acc0[4] = {0.f, 0.f, 0.f, 0.f};
    float acc1[4] = {0.f, 0.f, 0.f, 0.f};

    #pragma unroll
    for (int kc = 0; kc < FEAT; kc += 64) {
        #pragma unroll
        for (int s = 0; s < 2; s++) {
            int t = tid + s * 256;
            int r = t >> 4, k4 = t & 15;
            *(float4*)&Xs[r * PP + k4 * 4] =
                *(const float4*)&X[(size_t)(rbase + r) * FEAT + kc + k4 * 4];
        }
        #pragma unroll
        for (int s = 0; s < 16; s++) {
            int t = tid + s * 256;
            int k = t >> 6, j = t & 63;
            Wt[j * PP + k] = W[(kc + k) * HID + j];
        }
        __syncthreads();

        #pragma unroll 4
        for (int k0 = 0; k0 < 64; k0 += 4) {
            float4 x0 = *(const float4*)&Xs[rg * PP + k0];
            float4 x1 = *(const float4*)&Xs[(rg + 16) * PP + k0];
            #pragma unroll
            for (int j = 0; j < 4; j++) {
                float4 wv = *(const float4*)&Wt[(cg + 16 * j) * PP + k0];
                acc0[j] += x0.x * wv.x; acc0[j] += x0.y * wv.y;
                acc0[j] += x0.z * wv.z; acc0[j] += x0.w * wv.w;
                acc1[j] += x1.x * wv.x; acc1[j] += x1.y * wv.y;
                acc1[j] += x1.z * wv.z; acc1[j] += x1.w * wv.w;
            }
        }
        __syncthreads();
    }

    int r0 = rbase + rg;
    int r1 = rbase + rg + 16;
    float d0 = 1.0f / g_deg[r0];
    float d1 = 1.0f / g_deg[r1];
    #pragma unroll
    for (int j = 0; j < 4; j++) {
        int c = cg + 16 * j;
        g_h1[(size_t)r0 * HID + c] = acc0[j];
        g_acc1[(size_t)r0 * HID + c] = acc0[j] * d0;
        g_h1[(size_t)r1 * HID + c] = acc1[j];
        g_acc1[(size_t)r1 * HID + c] = acc1[j] * d1;
    }
}

// ---------------- gemm2: h2 = h1act @ W2 ; acc2 = h2 / deg ------------------
__global__ void gemm2_kernel(const float* __restrict__ W) {
    __shared__ float Xs[32 * PP];
    __shared__ float Wt[64 * PP];
    const int tid = threadIdx.x;
    const int cg = tid & 15;
    const int rg = tid >> 4;
    const int rbase = blockIdx.x * 32;

    #pragma unroll
    for (int s = 0; s < 2; s++) {
        int t = tid + s * 256;
        int r = t >> 4, k4 = t & 15;
        *(float4*)&Xs[r * PP + k4 * 4] =
            *(const float4*)&g_h1[(size_t)(rbase + r) * HID + k4 * 4];
    }
    #pragma unroll
    for (int s = 0; s < 16; s++) {
        int t = tid + s * 256;
        int k = t >> 6, j = t & 63;
        Wt[j * PP + k] = W[k * HID + j];
    }
    __syncthreads();

    float acc0[4] = {0.f, 0.f, 0.f, 0.f};
    float acc1[4] = {0.f, 0.f, 0.f, 0.f};
    #pragma unroll 4
    for (int k0 = 0; k0 < HID; k0 += 4) {
        float4 x0 = *(const float4*)&Xs[rg * PP + k0];
        float4 x1 = *(const float4*)&Xs[(rg + 16) * PP + k0];
        #pragma unroll
        for (int j = 0; j < 4; j++) {
            float4 wv = *(const float4*)&Wt[(cg + 16 * j) * PP + k0];
            acc0[j] += x0.x * wv.x; acc0[j] += x0.y * wv.y;
            acc0[j] += x0.z * wv.z; acc0[j] += x0.w * wv.w;
            acc1[j] += x1.x * wv.x; acc1[j] += x1.y * wv.y;
            acc1[j] += x1.z * wv.z; acc1[j] += x1.w * wv.w;
        }
    }

    int r0 = rbase + rg;
    int r1 = rbase + rg + 16;
    float d0 = 1.0f / g_deg[r0];
    float d1 = 1.0f / g_deg[r1];
    #pragma unroll
    for (int j = 0; j < 4; j++) {
        int c = cg + 16 * j;
        g_h2[(size_t)r0 * HID + c] = acc0[j];
        g_acc2[(size_t)r0 * HID + c] = acc0[j] * d0;
        g_h2[(size_t)r1 * HID + c] = acc1[j];
        g_acc2[(size_t)r1 * HID + c] = acc1[j] * d1;
    }
}

// ---------------- gather: acc[c] += sum_{e->c} h[r]*norm  (no atomics) ------
// 256 thr = 16 nodes x 16 slices; slice p = tid&15 covers cols p*4..p*4+3.
__global__ void gather_kernel(int layer) {
    const float* h = layer ? g_h2 : g_h1;
    float* acc     = layer ? g_acc2 : g_acc1;
    int node = blockIdx.x * 16 + (threadIdx.x >> 4);
    int p = threadIdx.x & 15;
    if (node >= N_NODES) return;
    float* dst = acc + (size_t)node * HID + p * 4;
    float4 a = *(float4*)dst;   // self-loop term from gemm
    int i = g_start[node];
    int t = g_start[node + 1];
    for (; i + 1 < t; i += 2) {
        int r0 = g_er[i], r1 = g_er[i + 1];
        float n0 = g_en[i], n1 = g_en[i + 1];
        float4 v0 = *(const float4*)&h[(size_t)r0 * HID + p * 4];
        float4 v1 = *(const float4*)&h[(size_t)r1 * HID + p * 4];
        a.x += v0.x * n0 + v1.x * n1;
        a.y += v0.y * n0 + v1.y * n1;
        a.z += v0.z * n0 + v1.z * n1;
        a.w += v0.w * n0 + v1.w * n1;
    }
    if (i < t) {
        int r0 = g_er[i];
        float n0 = g_en[i];
        float4 v0 = *(const float4*)&h[(size_t)r0 * HID + p * 4];
        a.x += v0.x * n0; a.y += v0.y * n0; a.z += v0.z * n0; a.w += v0.w * n0;
    }
    *(float4*)dst = a;
}

// ---------------- BN stats: per-column sum & sumsq --------------------------
__global__ void stats_kernel(int layer) {
    const float* acc = layer ? g_acc2 : g_acc1;
    float* sum = g_sum + layer * 2 * HID;
    float* sq  = sum + HID;
    int j = threadIdx.x & 63;
    int g = threadIdx.x >> 6;
    int rend = min(blockIdx.x * 512 + 512, N_NODES);
    float s = 0.f, q = 0.f;
    for (int r = blockIdx.x * 512 + g; r < rend; r += 4) {
        float v = acc[(size_t)r * HID + j];
        s += v; q += v * v;
    }
    __shared__ float ss[4][HID], qq[4][HID];
    ss[g][j] = s; qq[g][j] = q;
    __syncthreads();
    if (g == 0) {
        s = ss[0][j] + ss[1][j] + ss[2][j] + ss[3][j];
        q = qq[0][j] + qq[1][j] + qq[2][j] + qq[3][j];
        atomicAdd(&sum[j], s);
        atomicAdd(&sq[j], q);
    }
}

// ---------------- BN+ReLU layer1 -> overwrite g_h1 (input of gemm2) ---------
__global__ void bnrelu1_kernel(const float* __restrict__ gamma, const float* __restrict__ beta) {
    int idx = blockIdx.x * 256 + threadIdx.x;
    if (idx >= N_NODES * HID) return;
    int j = idx & 63;
    float m   = g_sum[j] * (1.0f / N_NODES);
    float var = g_sum[HID + j] * (1.0f / N_NODES) - m * m;
    float inv = rsqrtf(var + EPS);
    float v = (g_acc1[idx] - m) * inv * gamma[j] + beta[j];
    g_h1[idx] = fmaxf(v, 0.0f);
}

// ---------------- BN+ReLU layer2 fused with segment-max ---------------------
__global__ void bnrelu2max_kernel(const int* __restrict__ batch,
                                  const float* __restrict__ gamma,
                                  const float* __restrict__ beta) {
    int j = threadIdx.x & 63;
    int g = threadIdx.x >> 6;
    int rbase = (blockIdx.x * 4 + g) * 8;
    if (rbase >= N_NODES) return;
    float m   = g_sum[2 * HID + j] * (1.0f / N_NODES);
    float var = g_sum[3 * HID + j] * (1.0f / N_NODES) - m * m;
    float inv = rsqrtf(var + EPS);
    float gj = gamma[j], bj = beta[j];
    int cur = -1;
    float mx = 0.f;
    #pragma unroll
    for (int k = 0; k < 8; k++) {
        int r = rbase + k;
        if (r >= N_NODES) break;
        int b = batch[r];
        float v = fmaxf((g_acc2[(size_t)r * HID + j] - m) * inv * gj + bj, 0.f);
        if (b != cur) {
            if (cur >= 0 && mx > 0.f) atomicMax(&g_gx[cur * HID + j], __float_as_uint(mx));
            cur = b; mx = v;
        } else {
            mx = fmaxf(mx, v);
        }
    }
    if (cur >= 0 && mx > 0.f) atomicMax(&g_gx[cur * HID + j], __float_as_uint(mx));
}

// ---------------- head: speed enc + route enc + MLP (one block, 64 thr) -----
__global__ void head_kernel(const float* __restrict__ speed, const float* __restrict__ route,
                            const float* __restrict__ sw, const float* __restrict__ sb,
                            const float* __restrict__ sg, const float* __restrict__ sbe,
                            const float* __restrict__ cw, const float* __restrict__ cb,
                            const float* __restrict__ rg, const float* __restrict__ rbe,
                            const float* __restrict__ rw, const float* __restrict__ rb,
                            const float* __restrict__ ow1, const float* __restrict__ ob1,
                            const float* __restrict__ og, const float* __restrict__ obe,
                            const float* __restrict__ ow2, const float* __restrict__ ob2,
                            float* __restrict__ out) {
    int b = threadIdx.x;  // 64 threads
    __shared__ float s_v[NB][4];
    __shared__ float s_rc[NB][10];
    __shared__ float s_o1[NB][16];
    __shared__ float s_m[16], s_i[16];

    float sp = speed[b];
    #pragma unroll
    for (int j = 0; j < 4; j++) s_v[b][j] = sp * sw[j] + sb[j];

    const float* rt = route + b * 20;
    #pragma unroll
    for (int t = 0; t < 10; t++) {
        float a = cb[0];
        #pragma unroll
        for (int k = 0; k < 3; k++) {
            int tau = t + k - 1;
            if (tau >= 0 && tau < 10) {
                a += rt[tau * 2 + 0] * cw[k];
                a += rt[tau * 2 + 1] * cw[3 + k];
            }
        }
        s_rc[b][t] = a;
    }
    __syncthreads();

    if (b < 4) {
        float s = 0.f, q = 0.f;
        for (int i = 0; i < NB; i++) { float v = s_v[i][b]; s += v; q += v * v; }
        float m = s / NB, var = q / NB - m * m;
        s_m[b] = m; s_i[b] = rsqrtf(var + EPS);
    }
    if (b == 8) {
        float s = 0.f, q = 0.f;
        for (int i = 0; i < NB; i++)
            for (int t = 0; t < 10; t++) { float v = s_rc[i][t]; s += v; q += v * v; }
        float m = s / 640.f, var = q / 640.f - m * m;
        s_m[8] = m; s_i[8] = rsqrtf(var + EPS);
    }
    __syncthreads();

    float vj[4];
    #pragma unroll
    for (int j = 0; j < 4; j++)
        vj[j] = fmaxf((s_v[b][j] - s_m[j]) * s_i[j] * sg[j] + sbe[j], 0.f);

    float rcn[10];
    #pragma unroll
    for (int t = 0; t < 10; t++)
        rcn[t] = fmaxf((s_rc[b][t] - s_m[8]) * s_i[8] * rg[0] + rbe[0], 0.f);

    float rj[4];
    #pragma unroll
    for (int j = 0; j < 4; j++) {
        float a = rb[j];
        #pragma unroll
        for (int t = 0; t < 10; t++) a += rcn[t] * rw[t * 4 + j];
        rj[j] = a;
    }

    #pragma unroll
    for (int j = 0; j < 16; j++) {
        float a = ob1[j];
        for (int k = 0; k < HID; k++)
            a += __uint_as_float(g_gx[b * HID + k]) * ow1[k * 16 + j];
        #pragma unroll
        for (int k = 0; k < 4; k++) a += vj[k] * ow1[(HID + k) * 16 + j];
        #pragma unroll
        for (int k = 0; k < 4; k++) a += rj[k] * ow1[(HID + 4 + k) * 16 + j];
        s_o1[b][j] = a;
    }
    __syncthreads();
    if (b < 16) {
        float s = 0.f, q = 0.f;
        for (int i = 0; i < NB; i++) { float v = s_o1[i][b]; s += v; q += v * v; }
        float m = s / NB, var = q / NB - m * m;
        s_m[b] = m; s_i[b] = rsqrtf(var + EPS);
    }
    __syncthreads();
    float on[16];
    #pragma unroll
    for (int j = 0; j < 16; j++)
        on[j] = fmaxf((s_o1[b][j] - s_m[j]) * s_i[j] * og[j] + obe[j], 0.f);
    #pragma unroll
    for (int a = 0; a < 5; a++) {
        float o = ob2[a];
        #pragma unroll
        for (int j = 0; j < 16; j++) o += on[j] * ow2[j * 5 + a];
        out[b * 5 + a] = o;
    }
}

// ---------------------------------------------------------------------------
extern "C" void kernel_launch(void* const* d_in, const int* in_sizes, int n_in,
                              void* d_out, int out_size) {
    const float* x    = (const float*)d_in[0];
    const int*   ei   = (const int*)d_in[1];
    const float* ew   = (const float*)d_in[2];
    const int*   bidx = (const int*)d_in[3];
    const float* speed = (const float*)d_in[4];
    const float* route = (const float*)d_in[5];
    const float* W1 = (const float*)d_in[6];
    const float* g1 = (const float*)d_in[8];
    const float* be1 = (const float*)d_in[9];
    const float* W2 = (const float*)d_in[10];
    const float* g2 = (const float*)d_in[12];
    const float* be2 = (const float*)d_in[13];
    const float* sw  = (const float*)d_in[14];
    const float* sb  = (const float*)d_in[15];
    const float* sg  = (const float*)d_in[16];
    const float* sbe = (const float*)d_in[17];
    const float* cw  = (const float*)d_in[18];
    const float* cb  = (const float*)d_in[19];
    const float* rg  = (const float*)d_in[20];
    const float* rbe = (const float*)d_in[21];
    const float* rw  = (const float*)d_in[22];
    const float* rb  = (const float*)d_in[23];
    const float* ow1 = (const float*)d_in[24];
    const float* ob1 = (const float*)d_in[25];
    const float* og  = (const float*)d_in[26];
    const float* obe = (const float*)d_in[27];
    const float* ow2 = (const float*)d_in[28];
    const float* ob2 = (const float*)d_in[29];
    float* out = (float*)d_out;

    const int* row = ei;            // edge_index[0]
    const int* col = ei + N_EDGES;  // edge_index[1]

    init_kernel<<<(N_NODES + 255) / 256, 256>>>();
    deg_kernel<<<(N_EDGES + 255) / 256, 256>>>(col, ew);
    norm_kernel<<<(N_EDGES + 255) / 256, 256>>>(row, col, ew);
    scan1_kernel<<<NBLK, 256>>>();
    scan2_kernel<<<1, 512>>>();
    scan3_kernel<<<NBLK, 256>>>();
    fill_kernel<<<(N_EDGES + 255) / 256, 256>>>(row, col);

    gemm1_kernel<<<N_NODES / 32, 256>>>(x, W1);
    gather_kernel<<<(N_NODES + 15) / 16, 256>>>(0);
    stats_kernel<<<(N_NODES + 511) / 512, 256>>>(0);
    bnrelu1_kernel<<<(N_NODES * HID + 255) / 256, 256>>>(g1, be1);

    gemm2_kernel<<<N_NODES / 32, 256>>>(W2);
    gather_kernel<<<(N_NODES + 15) / 16, 256>>>(1);
    stats_kernel<<<(N_NODES + 511) / 512, 256>>>(1);
    bnrelu2max_kernel<<<(N_NODES + 31) / 32, 256>>>(bidx, g2, be2);

    head_kernel<<<1, 64>>>(speed, route, sw, sb, sg, sbe, cw, cb, rg, rbe,
                           rw, rb, ow1, ob1, og, obe, ow2, ob2, out);
}

// round 11
// speedup vs baseline: 2.0109x; 1.2614x over previous
#include <cuda_runtime.h>
#include <cuda_bf16.h>

#define N_NODES 100000
#define N_EDGES 1600000
#define HID 64
#define FEAT 128
#define NB 64
#define EPS 1e-5f
#define NBLK 391   // ceil(N_NODES/256)

// ---------------- scratch (static device globals; no allocs) ----------------
__device__ float    g_deg[N_NODES];
__device__ float    g_h1[N_NODES * HID];
__device__ float    g_acc1[N_NODES * HID];
__device__ float    g_h2[N_NODES * HID];
__device__ float    g_acc2[N_NODES * HID];
__device__ float    g_sum[4 * HID];      // [sum1, sq1, sum2, sq2]
__device__ float    g_bnsc[HID];         // layer1 BN scale
__device__ float    g_bnsh[HID];         // layer1 BN shift
__device__ unsigned g_gx[NB * HID];      // segment-max (float bits, all >= 0)
// CSR build
__device__ int      g_cnt[N_NODES];
__device__ int      g_start[N_NODES + 1];
__device__ int      g_bsum[512];
__device__ int      g_cursor[N_NODES];
__device__ int      g_er[N_EDGES];       // permuted source row per incoming edge
__device__ float    g_en[N_EDGES];       // permuted norm per incoming edge

// ---------------- init: deg=1, zero stats/gx/cnt/cursor ---------------------
__global__ void init_kernel() {
    int i = blockIdx.x * 256 + threadIdx.x;
    if (i < N_NODES) { g_deg[i] = 1.0f; g_cnt[i] = 0; g_cursor[i] = 0; }
    if (i < 4 * HID) g_sum[i] = 0.0f;
    if (i < NB * HID) g_gx[i] = 0u;
    if (i == 0) g_start[N_NODES] = N_EDGES;
}

// ---------------- degree: deg[c] += w ; hist: cnt[c]++ ----------------------
__global__ void deg_kernel(const int* __restrict__ col, const float* __restrict__ w) {
    int e = blockIdx.x * 256 + threadIdx.x;
    if (e < N_EDGES) {
        int c = col[e];
        atomicAdd(&g_deg[c], w[e]);
        atomicAdd(&g_cnt[c], 1);
    }
}

// ---------------- exclusive scan of g_cnt -> g_start (3 kernels) ------------
__global__ void scan1_kernel() {
    __shared__ int sm[256];
    int i = blockIdx.x * 256 + threadIdx.x;
    int v = (i < N_NODES) ? g_cnt[i] : 0;
    sm[threadIdx.x] = v;
    __syncthreads();
    #pragma unroll
    for (int d = 1; d < 256; d <<= 1) {
        int t = (threadIdx.x >= d) ? sm[threadIdx.x - d] : 0;
        __syncthreads();
        sm[threadIdx.x] += t;
        __syncthreads();
    }
    if (i < N_NODES) g_start[i] = sm[threadIdx.x] - v;   // exclusive
    if (threadIdx.x == 255) g_bsum[blockIdx.x] = sm[255];
}
__global__ void scan2_kernel() {
    __shared__ int sm[512];
    int i = threadIdx.x;
    int v = (i < NBLK) ? g_bsum[i] : 0;
    sm[i] = v;
    __syncthreads();
    #pragma unroll
    for (int d = 1; d < 512; d <<= 1) {
        int t = (i >= d) ? sm[i - d] : 0;
        __syncthreads();
        sm[i] += t;
        __syncthreads();
    }
    if (i < NBLK) g_bsum[i] = sm[i] - v;                 // exclusive
}
__global__ void scan3_kernel() {
    int i = blockIdx.x * 256 + threadIdx.x;
    if (i < N_NODES) g_start[i] += g_bsum[blockIdx.x];
}

// ---------------- fill CSR: permute (row, norm-computed-inline) -------------
__global__ void fill_kernel(const int* __restrict__ row, const int* __restrict__ col,
                            const float* __restrict__ w) {
    int e = blockIdx.x * 256 + threadIdx.x;
    if (e >= N_EDGES) return;
    int c = col[e];
    int r = row[e];
    int p = atomicAdd(&g_cursor[c], 1);
    int i = g_start[c] + p;
    g_er[i] = r;
    g_en[i] = w[e] * rsqrtf(g_deg[r] * g_deg[c]);
}

// ---------------- gemm1: h1 = x @ W1 ; acc1 = h1 / deg ----------------------
// 64 rows x 64 cols per block, 256 thr = 16 rg x 16 cg, 4x4 per thread.
// Thread: rows {rg+16i}, cols {cg+16j}.  ~55 regs, 34.8 KB smem.
#define PP 68
__global__ void gemm1_kernel(const float* __restrict__ X, const float* __restrict__ W) {
    __shared__ float Xs[64 * PP];   // 17.4 KB
    __shared__ float Wt[64 * PP];   // 17.4 KB
    const int tid = threadIdx.x;
    const int cg = tid & 15;
    const int rg = tid >> 4;
    const int rbase = blockIdx.x * 64;

    float acc[4][4];
    #pragma unroll
    for (int i = 0; i < 4; i++)
        #pragma unroll
        for (int j = 0; j < 4; j++) acc[i][j] = 0.0f;

    #pragma unroll
    for (int kc = 0; kc < FEAT; kc += 64) {
        // stage X chunk: 64 rows x 64 k = 1024 float4, 4 per thread
        #pragma unroll
        for (int s = 0; s < 4; s++) {
            int t = tid + s * 256;
            int r = t >> 4, k4 = t & 15;
            int gr = rbase + r;
            if (gr >= N_NODES) gr = N_NODES - 1;
            *(float4*)&Xs[r * PP + k4 * 4] =
                *(const float4*)&X[(size_t)gr * FEAT + kc + k4 * 4];
        }
        // stage W chunk transposed: 4096 scalars, 16 per thread
        #pragma unroll
        for (int s = 0; s < 16; s++) {
            int t = tid + s * 256;
            int k = t >> 6, j = t & 63;
            Wt[j * PP + k] = W[(kc + k) * HID + j];
        }
        __syncthreads();

        #pragma unroll 4
        for (int k0 = 0; k0 < 64; k0 += 4) {
            float4 xv[4];
            #pragma unroll
            for (int i = 0; i < 4; i++)
                xv[i] = *(const float4*)&Xs[(rg + 16 * i) * PP + k0];
            #pragma unroll
            for (int j = 0; j < 4; j++) {
                float4 wv = *(const float4*)&Wt[(cg + 16 * j) * PP + k0];
                #pragma unroll
                for (int i = 0; i < 4; i++) {
                    acc[i][j] += xv[i].x * wv.x; acc[i][j] += xv[i].y * wv.y;
                    acc[i][j] += xv[i].z * wv.z; acc[i][j] += xv[i].w * wv.w;
                }
            }
        }
        __syncthreads();
    }

    #pragma unroll
    for (int i = 0; i < 4; i++) {
        int r = rbase + rg + 16 * i;
        if (r < N_NODES) {
            float d2 = 1.0f / g_deg[r];
            #pragma unroll
            for (int j = 0; j < 4; j++) {
                int c = cg + 16 * j;
                g_h1[(size_t)r * HID + c] = acc[i][j];
                g_acc1[(size_t)r * HID + c] = acc[i][j] * d2;
            }
        }
    }
}

// ---------------- bnprep: layer1 BN scale/shift from g_sum ------------------
__global__ void bnprep_kernel(const float* __restrict__ gamma, const float* __restrict__ beta) {
    int j = threadIdx.x;   // 64 threads
    float m   = g_sum[j] * (1.0f / N_NODES);
    float var = g_sum[HID + j] * (1.0f / N_NODES) - m * m;
    float inv = rsqrtf(var + EPS);
    float sc = inv * gamma[j];
    g_bnsc[j] = sc;
    g_bnsh[j] = beta[j] - m * sc;
}

// ---------------- gemm2: h2 = relu(bn(acc1)) @ W2 ; acc2 = h2 / deg ---------
// BN+ReLU applied on the fly while staging X (kills bnrelu1 kernel).
__global__ void gemm2_kernel(const float* __restrict__ W) {
    __shared__ float Xs[64 * PP];
    __shared__ float Wt[64 * PP];
    const int tid = threadIdx.x;
    const int cg = tid & 15;
    const int rg = tid >> 4;
    const int rbase = blockIdx.x * 64;

    // stage X: 64 rows x 64 k = 1024 float4, 4 per thread, BN+ReLU fused
    #pragma unroll
    for (int s = 0; s < 4; s++) {
        int t = tid + s * 256;
        int r = t >> 4, k4 = t & 15;
        int gr = rbase + r;
        if (gr >= N_NODES) gr = N_NODES - 1;
        float4 v = *(const float4*)&g_acc1[(size_t)gr * HID + k4 * 4];
        float4 sc = *(const float4*)&g_bnsc[k4 * 4];
        float4 sh = *(const float4*)&g_bnsh[k4 * 4];
        v.x = fmaxf(fmaf(v.x, sc.x, sh.x), 0.f);
        v.y = fmaxf(fmaf(v.y, sc.y, sh.y), 0.f);
        v.z = fmaxf(fmaf(v.z, sc.z, sh.z), 0.f);
        v.w = fmaxf(fmaf(v.w, sc.w, sh.w), 0.f);
        *(float4*)&Xs[r * PP + k4 * 4] = v;
    }
    #pragma unroll
    for (int s = 0; s < 16; s++) {
        int t = tid + s * 256;
        int k = t >> 6, j = t & 63;
        Wt[j * PP + k] = W[k * HID + j];
    }
    __syncthreads();

    float acc[4][4];
    #pragma unroll
    for (int i = 0; i < 4; i++)
        #pragma unroll
        for (int j = 0; j < 4; j++) acc[i][j] = 0.0f;

    #pragma unroll 4
    for (int k0 = 0; k0 < HID; k0 += 4) {
        float4 xv[4];
        #pragma unroll
        for (int i = 0; i < 4; i++)
            xv[i] = *(const float4*)&Xs[(rg + 16 * i) * PP + k0];
        #pragma unroll
        for (int j = 0; j < 4; j++) {
            float4 wv = *(const float4*)&Wt[(cg + 16 * j) * PP + k0];
            #pragma unroll
            for (int i = 0; i < 4; i++) {
                acc[i][j] += xv[i].x * wv.x; acc[i][j] += xv[i].y * wv.y;
                acc[i][j] += xv[i].z * wv.z; acc[i][j] += xv[i].w * wv.w;
            }
        }
    }

    #pragma unroll
    for (int i = 0; i < 4; i++) {
        int r = rbase + rg + 16 * i;
        if (r < N_NODES) {
            float d2 = 1.0f / g_deg[r];
            #pragma unroll
            for (int j = 0; j < 4; j++) {
                int c = cg + 16 * j;
                g_h2[(size_t)r * HID + c] = acc[i][j];
                g_acc2[(size_t)r * HID + c] = acc[i][j] * d2;
            }
        }
    }
}

// ---------------- gather + fused BN stats  (no atomics on features) ---------
// 256 thr = 16 nodes x 16 slices; slice p covers cols p*4..p*4+3.
// grid = 6250 exactly (100000/16): no tail, safe __syncthreads.
__global__ void gather_kernel(int layer) {
    const float* h = layer ? g_h2 : g_h1;
    float* acc     = layer ? g_acc2 : g_acc1;
    __shared__ float ssum[16 * HID];
    __shared__ float ssq[16 * HID];
    int ng = threadIdx.x >> 4;
    int p = threadIdx.x & 15;
    int node = blockIdx.x * 16 + ng;
    float* dst = acc + (size_t)node * HID + p * 4;
    float4 a = *(float4*)dst;   // self-loop term from gemm
    int i = g_start[node];
    int t = g_start[node + 1];
    for (; i + 1 < t; i += 2) {
        int r0 = g_er[i], r1 = g_er[i + 1];
        float n0 = g_en[i], n1 = g_en[i + 1];
        float4 v0 = *(const float4*)&h[(size_t)r0 * HID + p * 4];
        float4 v1 = *(const float4*)&h[(size_t)r1 * HID + p * 4];
        a.x += v0.x * n0 + v1.x * n1;
        a.y += v0.y * n0 + v1.y * n1;
        a.z += v0.z * n0 + v1.z * n1;
        a.w += v0.w * n0 + v1.w * n1;
    }
    if (i < t) {
        int r0 = g_er[i];
        float n0 = g_en[i];
        float4 v0 = *(const float4*)&h[(size_t)r0 * HID + p * 4];
        a.x += v0.x * n0; a.y += v0.y * n0; a.z += v0.z * n0; a.w += v0.w * n0;
    }
    *(float4*)dst = a;
    // fused BN stats
    ssum[ng * HID + p * 4 + 0] = a.x; ssq[ng * HID + p * 4 + 0] = a.x * a.x;
    ssum[ng * HID + p * 4 + 1] = a.y; ssq[ng * HID + p * 4 + 1] = a.y * a.y;
    ssum[ng * HID + p * 4 + 2] = a.z; ssq[ng * HID + p * 4 + 2] = a.z * a.z;
    ssum[ng * HID + p * 4 + 3] = a.w; ssq[ng * HID + p * 4 + 3] = a.w * a.w;
    __syncthreads();
    float* sums = g_sum + layer * 2 * HID;
    if (threadIdx.x < 64) {
        int j = threadIdx.x;
        float s = 0.f;
        #pragma unroll
        for (int r = 0; r < 16; r++) s += ssum[r * HID + j];
        atomicAdd(&sums[j], s);
    } else if (threadIdx.x < 128) {
        int j = threadIdx.x - 64;
        float q = 0.f;
        #pragma unroll
        for (int r = 0; r < 16; r++) q += ssq[r * HID + j];
        atomicAdd(&sums[HID + j], q);
    }
}

// ---------------- BN+ReLU layer2 fused with segment-max ---------------------
__global__ void bnrelu2max_kernel(const int* __restrict__ batch,
                                  const float* __restrict__ gamma,
                                  const float* __restrict__ beta) {
    int j = threadIdx.x & 63;
    int g = threadIdx.x >> 6;
    int rbase = (blockIdx.x * 4 + g) * 8;
    if (rbase >= N_NODES) return;
    float m   = g_sum[2 * HID + j] * (1.0f / N_NODES);
    float var = g_sum[3 * HID + j] * (1.0f / N_NODES) - m * m;
    float inv = rsqrtf(var + EPS);
    float gj = gamma[j], bj = beta[j];
    int cur = -1;
    float mx = 0.f;
    #pragma unroll
    for (int k = 0; k < 8; k++) {
        int r = rbase + k;
        if (r >= N_NODES) break;
        int b = batch[r];
        float v = fmaxf((g_acc2[(size_t)r * HID + j] - m) * inv * gj + bj, 0.f);
        if (b != cur) {
            if (cur >= 0 && mx > 0.f) atomicMax(&g_gx[cur * HID + j], __float_as_uint(mx));
            cur = b; mx = v;
        } else {
            mx = fmaxf(mx, v);
        }
    }
    if (cur >= 0 && mx > 0.f) atomicMax(&g_gx[cur * HID + j], __float_as_uint(mx));
}

// ---------------- head: speed enc + route enc + MLP (one block, 64 thr) -----
__global__ void head_kernel(const float* __restrict__ speed, const float* __restrict__ route,
                            const float* __restrict__ sw, const float* __restrict__ sb,
                            const float* __restrict__ sg, const float* __restrict__ sbe,
                            const float* __restrict__ cw, const float* __restrict__ cb,
                            const float* __restrict__ rg, const float* __restrict__ rbe,
                            const float* __restrict__ rw, const float* __restrict__ rb,
                            const float* __restrict__ ow1, const float* __restrict__ ob1,
                            const float* __restrict__ og, const float* __restrict__ obe,
                            const float* __restrict__ ow2, const float* __restrict__ ob2,
                            float* __restrict__ out) {
    int b = threadIdx.x;  // 64 threads
    __shared__ float s_v[NB][4];
    __shared__ float s_rc[NB][10];
    __shared__ float s_o1[NB][16];
    __shared__ float s_m[16], s_i[16];

    float sp = speed[b];
    #pragma unroll
    for (int j = 0; j < 4; j++) s_v[b][j] = sp * sw[j] + sb[j];

    const float* rt = route + b * 20;
    #pragma unroll
    for (int t = 0; t < 10; t++) {
        float a = cb[0];
        #pragma unroll
        for (int k = 0; k < 3; k++) {
            int tau = t + k - 1;
            if (tau >= 0 && tau < 10) {
                a += rt[tau * 2 + 0] * cw[k];
                a += rt[tau * 2 + 1] * cw[3 + k];
            }
        }
        s_rc[b][t] = a;
    }
    __syncthreads();

    if (b < 4) {
        float s = 0.f, q = 0.f;
        for (int i = 0; i < NB; i++) { float v = s_v[i][b]; s += v; q += v * v; }
        float m = s / NB, var = q / NB - m * m;
        s_m[b] = m; s_i[b] = rsqrtf(var + EPS);
    }
    if (b == 8) {
        float s = 0.f, q = 0.f;
        for (int i = 0; i < NB; i++)
            for (int t = 0; t < 10; t++) { float v = s_rc[i][t]; s += v; q += v * v; }
        float m = s / 640.f, var = q / 640.f - m * m;
        s_m[8] = m; s_i[8] = rsqrtf(var + EPS);
    }
    __syncthreads();

    float vj[4];
    #pragma unroll
    for (int j = 0; j < 4; j++)
        vj[j] = fmaxf((s_v[b][j] - s_m[j]) * s_i[j] * sg[j] + sbe[j], 0.f);

    float rcn[10];
    #pragma unroll
    for (int t = 0; t < 10; t++)
        rcn[t] = fmaxf((s_rc[b][t] - s_m[8]) * s_i[8] * rg[0] + rbe[0], 0.f);

    float rj[4];
    #pragma unroll
    for (int j = 0; j < 4; j++) {
        float a = rb[j];
        #pragma unroll
        for (int t = 0; t < 10; t++) a += rcn[t] * rw[t * 4 + j];
        rj[j] = a;
    }

    #pragma unroll
    for (int j = 0; j < 16; j++) {
        float a = ob1[j];
        for (int k = 0; k < HID; k++)
            a += __uint_as_float(g_gx[b * HID + k]) * ow1[k * 16 + j];
        #pragma unroll
        for (int k = 0; k < 4; k++) a += vj[k] * ow1[(HID + k) * 16 + j];
        #pragma unroll
        for (int k = 0; k < 4; k++) a += rj[k] * ow1[(HID + 4 + k) * 16 + j];
        s_o1[b][j] = a;
    }
    __syncthreads();
    if (b < 16) {
        float s = 0.f, q = 0.f;
        for (int i = 0; i < NB; i++) { float v = s_o1[i][b]; s += v; q += v * v; }
        float m = s / NB, var = q / NB - m * m;
        s_m[b] = m; s_i[b] = rsqrtf(var + EPS);
    }
    __syncthreads();
    float on[16];
    #pragma unroll
    for (int j = 0; j < 16; j++)
        on[j] = fmaxf((s_o1[b][j] - s_m[j]) * s_i[j] * og[j] + obe[j], 0.f);
    #pragma unroll
    for (int a = 0; a < 5; a++) {
        float o = ob2[a];
        #pragma unroll
        for (int j = 0; j < 16; j++) o += on[j] * ow2[j * 5 + a];
        out[b * 5 + a] = o;
    }
}

// ---------------------------------------------------------------------------
extern "C" void kernel_launch(void* const* d_in, const int* in_sizes, int n_in,
                              void* d_out, int out_size) {
    const float* x    = (const float*)d_in[0];
    const int*   ei   = (const int*)d_in[1];
    const float* ew   = (const float*)d_in[2];
    const int*   bidx = (const int*)d_in[3];
    const float* speed = (const float*)d_in[4];
    const float* route = (const float*)d_in[5];
    const float* W1 = (const float*)d_in[6];
    const float* g1 = (const float*)d_in[8];
    const float* be1 = (const float*)d_in[9];
    const float* W2 = (const float*)d_in[10];
    const float* g2 = (const float*)d_in[12];
    const float* be2 = (const float*)d_in[13];
    const float* sw  = (const float*)d_in[14];
    const float* sb  = (const float*)d_in[15];
    const float* sg  = (const float*)d_in[16];
    const float* sbe = (const float*)d_in[17];
    const float* cw  = (const float*)d_in[18];
    const float* cb  = (const float*)d_in[19];
    const float* rg  = (const float*)d_in[20];
    const float* rbe = (const float*)d_in[21];
    const float* rw  = (const float*)d_in[22];
    const float* rb  = (const float*)d_in[23];
    const float* ow1 = (const float*)d_in[24];
    const float* ob1 = (const float*)d_in[25];
    const float* og  = (const float*)d_in[26];
    const float* obe = (const float*)d_in[27];
    const float* ow2 = (const float*)d_in[28];
    const float* ob2 = (const float*)d_in[29];
    float* out = (float*)d_out;

    const int* row = ei;            // edge_index[0]
    const int* col = ei + N_EDGES;  // edge_index[1]

    init_kernel<<<(N_NODES + 255) / 256, 256>>>();
    deg_kernel<<<(N_EDGES + 255) / 256, 256>>>(col, ew);
    scan1_kernel<<<NBLK, 256>>>();
    scan2_kernel<<<1, 512>>>();
    scan3_kernel<<<NBLK, 256>>>();
    fill_kernel<<<(N_EDGES + 255) / 256, 256>>>(row, col, ew);

    gemm1_kernel<<<(N_NODES + 63) / 64, 256>>>(x, W1);
    gather_kernel<<<N_NODES / 16, 256>>>(0);
    bnprep_kernel<<<1, 64>>>(g1, be1);

    gemm2_kernel<<<(N_NODES + 63) / 64, 256>>>(W2);
    gather_kernel<<<N_NODES / 16, 256>>>(1);
    bnrelu2max_kernel<<<(N_NODES + 31) / 32, 256>>>(bidx, g2, be2);

    head_kernel<<<1, 64>>>(speed, route, sw, sb, sg, sbe, cw, cb, rg, rbe,
                           rw, rb, ow1, ob1, og, obe, ow2, ob2, out);
}

// round 12
// speedup vs baseline: 2.1978x; 1.0930x over previous
#include <cuda_runtime.h>
#include <cuda_bf16.h>
#include <cuda_fp16.h>

#define N_NODES 100000
#define N_EDGES 1600000
#define HID 64
#define FEAT 128
#define NB 64
#define EPS 1e-5f
#define NBLK 391   // ceil(N_NODES/256)

// ---------------- scratch (static device globals; no allocs) ----------------
__device__ float    g_deg[N_NODES];
__device__ __half   g_h1h[N_NODES * HID];   // fp16 messages, layer1
__device__ __half   g_h2h[N_NODES * HID];   // fp16 messages, layer2
__device__ float    g_acc1[N_NODES * HID];
__device__ float    g_acc2[N_NODES * HID];
__device__ float    g_sum[4 * HID];      // [sum1, sq1, sum2, sq2]
__device__ float    g_bnsc[HID];         // layer1 BN scale
__device__ float    g_bnsh[HID];         // layer1 BN shift
__device__ unsigned g_gx[NB * HID];      // segment-max (float bits, all >= 0)
// CSR build
__device__ int      g_cnt[N_NODES];
__device__ int      g_start[N_NODES + 1];
__device__ int      g_bsum[512];
__device__ int      g_cursor[N_NODES];
__device__ int      g_er[N_EDGES];       // permuted source row per incoming edge
__device__ float    g_en[N_EDGES];       // permuted norm per incoming edge

// ---------------- init: deg=1, zero stats/gx/cnt/cursor ---------------------
__global__ void init_kernel() {
    int i = blockIdx.x * 256 + threadIdx.x;
    if (i < N_NODES) { g_deg[i] = 1.0f; g_cnt[i] = 0; g_cursor[i] = 0; }
    if (i < 4 * HID) g_sum[i] = 0.0f;
    if (i < NB * HID) g_gx[i] = 0u;
    if (i == 0) g_start[N_NODES] = N_EDGES;
}

// ---------------- degree: deg[c] += w ; hist: cnt[c]++ ----------------------
__global__ void deg_kernel(const int* __restrict__ col, const float* __restrict__ w) {
    int e = blockIdx.x * 256 + threadIdx.x;
    if (e < N_EDGES) {
        int c = col[e];
        atomicAdd(&g_deg[c], w[e]);
        atomicAdd(&g_cnt[c], 1);
    }
}

// ---------------- exclusive scan of g_cnt -> g_start (3 kernels) ------------
__global__ void scan1_kernel() {
    __shared__ int sm[256];
    int i = blockIdx.x * 256 + threadIdx.x;
    int v = (i < N_NODES) ? g_cnt[i] : 0;
    sm[threadIdx.x] = v;
    __syncthreads();
    #pragma unroll
    for (int d = 1; d < 256; d <<= 1) {
        int t = (threadIdx.x >= d) ? sm[threadIdx.x - d] : 0;
        __syncthreads();
        sm[threadIdx.x] += t;
        __syncthreads();
    }
    if (i < N_NODES) g_start[i] = sm[threadIdx.x] - v;   // exclusive
    if (threadIdx.x == 255) g_bsum[blockIdx.x] = sm[255];
}
__global__ void scan2_kernel() {
    __shared__ int sm[512];
    int i = threadIdx.x;
    int v = (i < NBLK) ? g_bsum[i] : 0;
    sm[i] = v;
    __syncthreads();
    #pragma unroll
    for (int d = 1; d < 512; d <<= 1) {
        int t = (i >= d) ? sm[i - d] : 0;
        __syncthreads();
        sm[i] += t;
        __syncthreads();
    }
    if (i < NBLK) g_bsum[i] = sm[i] - v;                 // exclusive
}
__global__ void scan3_kernel() {
    int i = blockIdx.x * 256 + threadIdx.x;
    if (i < N_NODES) g_start[i] += g_bsum[blockIdx.x];
}

// ---------------- fill CSR: permute (row, norm-computed-inline) -------------
__global__ void fill_kernel(const int* __restrict__ row, const int* __restrict__ col,
                            const float* __restrict__ w) {
    int e = blockIdx.x * 256 + threadIdx.x;
    if (e >= N_EDGES) return;
    int c = col[e];
    int r = row[e];
    int p = atomicAdd(&g_cursor[c], 1);
    int i = g_start[c] + p;
    g_er[i] = r;
    g_en[i] = w[e] * rsqrtf(g_deg[r] * g_deg[c]);
}

// ---------------- gemm1: h1 = x @ W1 (fp16) ; acc1 = h1 / deg (fp32) --------
// 64 rows x 64 cols per block, 256 thr = 16 rg x 16 cg, 4x4 per thread.
#define PP 68
__global__ void gemm1_kernel(const float* __restrict__ X, const float* __restrict__ W) {
    __shared__ float Xs[64 * PP];   // 17.4 KB
    __shared__ float Wt[64 * PP];   // 17.4 KB
    const int tid = threadIdx.x;
    const int cg = tid & 15;
    const int rg = tid >> 4;
    const int rbase = blockIdx.x * 64;

    float acc[4][4];
    #pragma unroll
    for (int i = 0; i < 4; i++)
        #pragma unroll
        for (int j = 0; j < 4; j++) acc[i][j] = 0.0f;

    #pragma unroll
    for (int kc = 0; kc < FEAT; kc += 64) {
        #pragma unroll
        for (int s = 0; s < 4; s++) {
            int t = tid + s * 256;
            int r = t >> 4, k4 = t & 15;
            int gr = rbase + r;
            if (gr >= N_NODES) gr = N_NODES - 1;
            *(float4*)&Xs[r * PP + k4 * 4] =
                *(const float4*)&X[(size_t)gr * FEAT + kc + k4 * 4];
        }
        #pragma unroll
        for (int s = 0; s < 16; s++) {
            int t = tid + s * 256;
            int k = t >> 6, j = t & 63;
            Wt[j * PP + k] = W[(kc + k) * HID + j];
        }
        __syncthreads();

        #pragma unroll 4
        for (int k0 = 0; k0 < 64; k0 += 4) {
            float4 xv[4];
            #pragma unroll
            for (int i = 0; i < 4; i++)
                xv[i] = *(const float4*)&Xs[(rg + 16 * i) * PP + k0];
            #pragma unroll
            for (int j = 0; j < 4; j++) {
                float4 wv = *(const float4*)&Wt[(cg + 16 * j) * PP + k0];
                #pragma unroll
                for (int i = 0; i < 4; i++) {
                    acc[i][j] += xv[i].x * wv.x; acc[i][j] += xv[i].y * wv.y;
                    acc[i][j] += xv[i].z * wv.z; acc[i][j] += xv[i].w * wv.w;
                }
            }
        }
        __syncthreads();
    }

    #pragma unroll
    for (int i = 0; i < 4; i++) {
        int r = rbase + rg + 16 * i;
        if (r < N_NODES) {
            float d2 = 1.0f / g_deg[r];
            #pragma unroll
            for (int j = 0; j < 4; j++) {
                int c = cg + 16 * j;
                g_h1h[(size_t)r * HID + c] = __float2half_rn(acc[i][j]);
                g_acc1[(size_t)r * HID + c] = acc[i][j] * d2;
            }
        }
    }
}

// ---------------- bnprep: layer1 BN scale/shift from g_sum ------------------
__global__ void bnprep_kernel(const float* __restrict__ gamma, const float* __restrict__ beta) {
    int j = threadIdx.x;   // 64 threads
    float m   = g_sum[j] * (1.0f / N_NODES);
    float var = g_sum[HID + j] * (1.0f / N_NODES) - m * m;
    float inv = rsqrtf(var + EPS);
    float sc = inv * gamma[j];
    g_bnsc[j] = sc;
    g_bnsh[j] = beta[j] - m * sc;
}

// ---------------- gemm2: h2 = relu(bn(acc1)) @ W2 ; acc2 = h2 / deg ---------
__global__ void gemm2_kernel(const float* __restrict__ W) {
    __shared__ float Xs[64 * PP];
    __shared__ float Wt[64 * PP];
    const int tid = threadIdx.x;
    const int cg = tid & 15;
    const int rg = tid >> 4;
    const int rbase = blockIdx.x * 64;

    // stage X: BN+ReLU fused
    #pragma unroll
    for (int s = 0; s < 4; s++) {
        int t = tid + s * 256;
        int r = t >> 4, k4 = t & 15;
        int gr = rbase + r;
        if (gr >= N_NODES) gr = N_NODES - 1;
        float4 v = *(const float4*)&g_acc1[(size_t)gr * HID + k4 * 4];
        float4 sc = *(const float4*)&g_bnsc[k4 * 4];
        float4 sh = *(const float4*)&g_bnsh[k4 * 4];
        v.x = fmaxf(fmaf(v.x, sc.x, sh.x), 0.f);
        v.y = fmaxf(fmaf(v.y, sc.y, sh.y), 0.f);
        v.z = fmaxf(fmaf(v.z, sc.z, sh.z), 0.f);
        v.w = fmaxf(fmaf(v.w, sc.w, sh.w), 0.f);
        *(float4*)&Xs[r * PP + k4 * 4] = v;
    }
    #pragma unroll
    for (int s = 0; s < 16; s++) {
        int t = tid + s * 256;
        int k = t >> 6, j = t & 63;
        Wt[j * PP + k] = W[k * HID + j];
    }
    __syncthreads();

    float acc[4][4];
    #pragma unroll
    for (int i = 0; i < 4; i++)
        #pragma unroll
        for (int j = 0; j < 4; j++) acc[i][j] = 0.0f;

    #pragma unroll 4
    for (int k0 = 0; k0 < HID; k0 += 4) {
        float4 xv[4];
        #pragma unroll
        for (int i = 0; i < 4; i++)
            xv[i] = *(const float4*)&Xs[(rg + 16 * i) * PP + k0];
        #pragma unroll
        for (int j = 0; j < 4; j++) {
            float4 wv = *(const float4*)&Wt[(cg + 16 * j) * PP + k0];
            #pragma unroll
            for (int i = 0; i < 4; i++) {
                acc[i][j] += xv[i].x * wv.x; acc[i][j] += xv[i].y * wv.y;
                acc[i][j] += xv[i].z * wv.z; acc[i][j] += xv[i].w * wv.w;
            }
        }
    }

    #pragma unroll
    for (int i = 0; i < 4; i++) {
        int r = rbase + rg + 16 * i;
        if (r < N_NODES) {
            float d2 = 1.0f / g_deg[r];
            #pragma unroll
            for (int j = 0; j < 4; j++) {
                int c = cg + 16 * j;
                g_h2h[(size_t)r * HID + c] = __float2half_rn(acc[i][j]);
                g_acc2[(size_t)r * HID + c] = acc[i][j] * d2;
            }
        }
    }
}

// ---------------- gather (fp16 messages) + fused BN stats -------------------
// 256 thr = 16 nodes x 16 slices; slice p covers cols p*4..p*4+3 (8 B loads).
__global__ void gather_kernel(int layer) {
    const __half* h = layer ? g_h2h : g_h1h;
    float* acc      = layer ? g_acc2 : g_acc1;
    __shared__ float ssum[16 * HID];
    __shared__ float ssq[16 * HID];
    int ng = threadIdx.x >> 4;
    int p = threadIdx.x & 15;
    int node = blockIdx.x * 16 + ng;
    float* dst = acc + (size_t)node * HID + p * 4;
    float4 a = *(float4*)dst;   // self-loop term from gemm (fp32)
    int i = g_start[node];
    int t = g_start[node + 1];
    for (; i + 1 < t; i += 2) {
        int r0 = g_er[i], r1 = g_er[i + 1];
        float n0 = g_en[i], n1 = g_en[i + 1];
        __half2 u0 = *(const __half2*)&h[(size_t)r0 * HID + p * 4];
        __half2 u1 = *(const __half2*)&h[(size_t)r0 * HID + p * 4 + 2];
        __half2 v0 = *(const __half2*)&h[(size_t)r1 * HID + p * 4];
        __half2 v1 = *(const __half2*)&h[(size_t)r1 * HID + p * 4 + 2];
        float2 f0 = __half22float2(u0), f1 = __half22float2(u1);
        float2 g0 = __half22float2(v0), g1 = __half22float2(v1);
        a.x += f0.x * n0 + g0.x * n1;
        a.y += f0.y * n0 + g0.y * n1;
        a.z += f1.x * n0 + g1.x * n1;
        a.w += f1.y * n0 + g1.y * n1;
    }
    if (i < t) {
        int r0 = g_er[i];
        float n0 = g_en[i];
        __half2 u0 = *(const __half2*)&h[(size_t)r0 * HID + p * 4];
        __half2 u1 = *(const __half2*)&h[(size_t)r0 * HID + p * 4 + 2];
        float2 f0 = __half22float2(u0), f1 = __half22float2(u1);
        a.x += f0.x * n0; a.y += f0.y * n0; a.z += f1.x * n0; a.w += f1.y * n0;
    }
    *(float4*)dst = a;
    // fused BN stats
    ssum[ng * HID + p * 4 + 0] = a.x; ssq[ng * HID + p * 4 + 0] = a.x * a.x;
    ssum[ng * HID + p * 4 + 1] = a.y; ssq[ng * HID + p * 4 + 1] = a.y * a.y;
    ssum[ng * HID + p * 4 + 2] = a.z; ssq[ng * HID + p * 4 + 2] = a.z * a.z;
    ssum[ng * HID + p * 4 + 3] = a.w; ssq[ng * HID + p * 4 + 3] = a.w * a.w;
    __syncthreads();
    float* sums = g_sum + layer * 2 * HID;
    if (threadIdx.x < 64) {
        int j = threadIdx.x;
        float s = 0.f;
        #pragma unroll
        for (int r = 0; r < 16; r++) s += ssum[r * HID + j];
        atomicAdd(&sums[j], s);
    } else if (threadIdx.x < 128) {
        int j = threadIdx.x - 64;
        float q = 0.f;
        #pragma unroll
        for (int r = 0; r < 16; r++) q += ssq[r * HID + j];
        atomicAdd(&sums[HID + j], q);
    }
}

// ---------------- BN+ReLU layer2 fused with segment-max ---------------------
__global__ void bnrelu2max_kernel(const int* __restrict__ batch,
                                  const float* __restrict__ gamma,
                                  const float* __restrict__ beta) {
    int j = threadIdx.x & 63;
    int g = threadIdx.x >> 6;
    int rbase = (blockIdx.x * 4 + g) * 8;
    if (rbase >= N_NODES) return;
    float m   = g_sum[2 * HID + j] * (1.0f / N_NODES);
    float var = g_sum[3 * HID + j] * (1.0f / N_NODES) - m * m;
    float inv = rsqrtf(var + EPS);
    float gj = gamma[j], bj = beta[j];
    int cur = -1;
    float mx = 0.f;
    #pragma unroll
    for (int k = 0; k < 8; k++) {
        int r = rbase + k;
        if (r >= N_NODES) break;
        int b = batch[r];
        float v = fmaxf((g_acc2[(size_t)r * HID + j] - m) * inv * gj + bj, 0.f);
        if (b != cur) {
            if (cur >= 0 && mx > 0.f) atomicMax(&g_gx[cur * HID + j], __float_as_uint(mx));
            cur = b; mx = v;
        } else {
            mx = fmaxf(mx, v);
        }
    }
    if (cur >= 0 && mx > 0.f) atomicMax(&g_gx[cur * HID + j], __float_as_uint(mx));
}

// ---------------- head: speed enc + route enc + MLP (one block, 64 thr) -----
__global__ void head_kernel(const float* __restrict__ speed, const float* __restrict__ route,
                            const float* __restrict__ sw, const float* __restrict__ sb,
                            const float* __restrict__ sg, const float* __restrict__ sbe,
                            const float* __restrict__ cw, const float* __restrict__ cb,
                            const float* __restrict__ rg, const float* __restrict__ rbe,
                            const float* __restrict__ rw, const float* __restrict__ rb,
                            const float* __restrict__ ow1, const float* __restrict__ ob1,
                            const float* __restrict__ og, const float* __restrict__ obe,
                            const float* __restrict__ ow2, const float* __restrict__ ob2,
                            float* __restrict__ out) {
    int b = threadIdx.x;  // 64 threads
    __shared__ float s_v[NB][4];
    __shared__ float s_rc[NB][10];
    __shared__ float s_o1[NB][16];
    __shared__ float s_m[16], s_i[16];

    float sp = speed[b];
    #pragma unroll
    for (int j = 0; j < 4; j++) s_v[b][j] = sp * sw[j] + sb[j];

    const float* rt = route + b * 20;
    #pragma unroll
    for (int t = 0; t < 10; t++) {
        float a = cb[0];
        #pragma unroll
        for (int k = 0; k < 3; k++) {
            int tau = t + k - 1;
            if (tau >= 0 && tau < 10) {
                a += rt[tau * 2 + 0] * cw[k];
                a += rt[tau * 2 + 1] * cw[3 + k];
            }
        }
        s_rc[b][t] = a;
    }
    __syncthreads();

    if (b < 4) {
        float s = 0.f, q = 0.f;
        for (int i = 0; i < NB; i++) { float v = s_v[i][b]; s += v; q += v * v; }
        float m = s / NB, var = q / NB - m * m;
        s_m[b] = m; s_i[b] = rsqrtf(var + EPS);
    }
    if (b == 8) {
        float s = 0.f, q = 0.f;
        for (int i = 0; i < NB; i++)
            for (int t = 0; t < 10; t++) { float v = s_rc[i][t]; s += v; q += v * v; }
        float m = s / 640.f, var = q / 640.f - m * m;
        s_m[8] = m; s_i[8] = rsqrtf(var + EPS);
    }
    __syncthreads();

    float vj[4];
    #pragma unroll
    for (int j = 0; j < 4; j++)
        vj[j] = fmaxf((s_v[b][j] - s_m[j]) * s_i[j] * sg[j] + sbe[j], 0.f);

    float rcn[10];
    #pragma unroll
    for (int t = 0; t < 10; t++)
        rcn[t] = fmaxf((s_rc[b][t] - s_m[8]) * s_i[8] * rg[0] + rbe[0], 0.f);

    float rj[4];
    #pragma unroll
    for (int j = 0; j < 4; j++) {
        float a = rb[j];
        #pragma unroll
        for (int t = 0; t < 10; t++) a += rcn[t] * rw[t * 4 + j];
        rj[j] = a;
    }

    #pragma unroll
    for (int j = 0; j < 16; j++) {
        float a = ob1[j];
        for (int k = 0; k < HID; k++)
            a += __uint_as_float(g_gx[b * HID + k]) * ow1[k * 16 + j];
        #pragma unroll
        for (int k = 0; k < 4; k++) a += vj[k] * ow1[(HID + k) * 16 + j];
        #pragma unroll
        for (int k = 0; k < 4; k++) a += rj[k] * ow1[(HID + 4 + k) * 16 + j];
        s_o1[b][j] = a;
    }
    __syncthreads();
    if (b < 16) {
        float s = 0.f, q = 0.f;
        for (int i = 0; i < NB; i++) { float v = s_o1[i][b]; s += v; q += v * v; }
        float m = s / NB, var = q / NB - m * m;
        s_m[b] = m; s_i[b] = rsqrtf(var + EPS);
    }
    __syncthreads();
    float on[16];
    #pragma unroll
    for (int j = 0; j < 16; j++)
        on[j] = fmaxf((s_o1[b][j] - s_m[j]) * s_i[j] * og[j] + obe[j], 0.f);
    #pragma unroll
    for (int a = 0; a < 5; a++) {
        float o = ob2[a];
        #pragma unroll
        for (int j = 0; j < 16; j++) o += on[j] * ow2[j * 5 + a];
        out[b * 5 + a] = o;
    }
}

// ---------------------------------------------------------------------------
extern "C" void kernel_launch(void* const* d_in, const int* in_sizes, int n_in,
                              void* d_out, int out_size) {
    const float* x    = (const float*)d_in[0];
    const int*   ei   = (const int*)d_in[1];
    const float* ew   = (const float*)d_in[2];
    const int*   bidx = (const int*)d_in[3];
    const float* speed = (const float*)d_in[4];
    const float* route = (const float*)d_in[5];
    const float* W1 = (const float*)d_in[6];
    const float* g1 = (const float*)d_in[8];
    const float* be1 = (const float*)d_in[9];
    const float* W2 = (const float*)d_in[10];
    const float* g2 = (const float*)d_in[12];
    const float* be2 = (const float*)d_in[13];
    const float* sw  = (const float*)d_in[14];
    const float* sb  = (const float*)d_in[15];
    const float* sg  = (const float*)d_in[16];
    const float* sbe = (const float*)d_in[17];
    const float* cw  = (const float*)d_in[18];
    const float* cb  = (const float*)d_in[19];
    const float* rg  = (const float*)d_in[20];
    const float* rbe = (const float*)d_in[21];
    const float* rw  = (const float*)d_in[22];
    const float* rb  = (const float*)d_in[23];
    const float* ow1 = (const float*)d_in[24];
    const float* ob1 = (const float*)d_in[25];
    const float* og  = (const float*)d_in[26];
    const float* obe = (const float*)d_in[27];
    const float* ow2 = (const float*)d_in[28];
    const float* ob2 = (const float*)d_in[29];
    float* out = (float*)d_out;

    const int* row = ei;            // edge_index[0]
    const int* col = ei + N_EDGES;  // edge_index[1]

    init_kernel<<<(N_NODES + 255) / 256, 256>>>();
    deg_kernel<<<(N_EDGES + 255) / 256, 256>>>(col, ew);
    scan1_kernel<<<NBLK, 256>>>();
    scan2_kernel<<<1, 512>>>();
    scan3_kernel<<<NBLK, 256>>>();
    fill_kernel<<<(N_EDGES + 255) / 256, 256>>>(row, col, ew);

    gemm1_kernel<<<(N_NODES + 63) / 64, 256>>>(x, W1);
    gather_kernel<<<N_NODES / 16, 256>>>(0);
    bnprep_kernel<<<1, 64>>>(g1, be1);

    gemm2_kernel<<<(N_NODES + 63) / 64, 256>>>(W2);
    gather_kernel<<<N_NODES / 16, 256>>>(1);
    bnrelu2max_kernel<<<(N_NODES + 31) / 32, 256>>>(bidx, g2, be2);

    head_kernel<<<1, 64>>>(speed, route, sw, sb, sg, sbe, cw, cb, rg, rbe,
                           rw, rb, ow1, ob1, og, obe, ow2, ob2, out);
}

// round 13
// speedup vs baseline: 2.2528x; 1.0250x over previous
#include <cuda_runtime.h>
#include <cuda_bf16.h>
#include <cuda_fp16.h>

#define N_NODES 100000
#define N_EDGES 1600000
#define HID 64
#define FEAT 128
#define NB 64
#define EPS 1e-5f
#define NBLK 391   // ceil(N_NODES/256)

// ---------------- scratch (static device globals; no allocs) ----------------
__device__ float    g_deg[N_NODES];
__device__ __half   g_h1h[N_NODES * HID];   // fp16 messages, layer1
__device__ __half   g_h2h[N_NODES * HID];   // fp16 messages, layer2
__device__ float    g_acc1[N_NODES * HID];
__device__ float    g_acc2[N_NODES * HID];
__device__ float    g_sum[4 * HID];      // [sum1, sq1, sum2, sq2]
__device__ float    g_bnsc[HID];         // layer1 BN scale
__device__ float    g_bnsh[HID];         // layer1 BN shift
__device__ unsigned g_gx[NB * HID];      // segment-max (float bits, all >= 0)
// CSR build
__device__ int      g_cnt[N_NODES];
__device__ int      g_start[N_NODES + 1];
__device__ int      g_bsum[512];
__device__ int      g_cursor[N_NODES];
__device__ int2     g_edge[N_EDGES];     // interleaved {src row, norm bits}

// ---------------- init: deg=1, zero stats/gx/cnt/cursor ---------------------
__global__ void init_kernel() {
    int i = blockIdx.x * 256 + threadIdx.x;
    if (i < N_NODES) { g_deg[i] = 1.0f; g_cnt[i] = 0; g_cursor[i] = 0; }
    if (i < 4 * HID) g_sum[i] = 0.0f;
    if (i < NB * HID) g_gx[i] = 0u;
    if (i == 0) g_start[N_NODES] = N_EDGES;
}

// ---------------- degree: deg[c] += w ; hist: cnt[c]++ ----------------------
__global__ void deg_kernel(const int* __restrict__ col, const float* __restrict__ w) {
    int e = blockIdx.x * 256 + threadIdx.x;
    if (e < N_EDGES) {
        int c = col[e];
        atomicAdd(&g_deg[c], w[e]);
        atomicAdd(&g_cnt[c], 1);
    }
}

// ---------------- exclusive scan of g_cnt -> g_start (3 kernels) ------------
__global__ void scan1_kernel() {
    __shared__ int sm[256];
    int i = blockIdx.x * 256 + threadIdx.x;
    int v = (i < N_NODES) ? g_cnt[i] : 0;
    sm[threadIdx.x] = v;
    __syncthreads();
    #pragma unroll
    for (int d = 1; d < 256; d <<= 1) {
        int t = (threadIdx.x >= d) ? sm[threadIdx.x - d] : 0;
        __syncthreads();
        sm[threadIdx.x] += t;
        __syncthreads();
    }
    if (i < N_NODES) g_start[i] = sm[threadIdx.x] - v;   // exclusive
    if (threadIdx.x == 255) g_bsum[blockIdx.x] = sm[255];
}
__global__ void scan2_kernel() {
    __shared__ int sm[512];
    int i = threadIdx.x;
    int v = (i < NBLK) ? g_bsum[i] : 0;
    sm[i] = v;
    __syncthreads();
    #pragma unroll
    for (int d = 1; d < 512; d <<= 1) {
        int t = (i >= d) ? sm[i - d] : 0;
        __syncthreads();
        sm[i] += t;
        __syncthreads();
    }
    if (i < NBLK) g_bsum[i] = sm[i] - v;                 // exclusive
}
__global__ void scan3_kernel() {
    int i = blockIdx.x * 256 + threadIdx.x;
    if (i < N_NODES) g_start[i] += g_bsum[blockIdx.x];
}

// ---------------- fill CSR: interleaved (row, norm) record ------------------
__global__ void fill_kernel(const int* __restrict__ row, const int* __restrict__ col,
                            const float* __restrict__ w) {
    int e = blockIdx.x * 256 + threadIdx.x;
    if (e >= N_EDGES) return;
    int c = col[e];
    int r = row[e];
    int p = atomicAdd(&g_cursor[c], 1);
    float nm = w[e] * rsqrtf(g_deg[r] * g_deg[c]);
    g_edge[g_start[c] + p] = make_int2(r, __float_as_int(nm));
}

// ---------------- gemm1: h1 = x @ W1 (fp16) ; acc1 = h1 / deg (fp32) --------
// 64 rows x 64 cols per block, 256 thr = 16 rg x 16 cg, 4x4 per thread.
#define PP 68
__global__ void gemm1_kernel(const float* __restrict__ X, const float* __restrict__ W) {
    __shared__ float Xs[64 * PP];   // 17.4 KB
    __shared__ float Wt[64 * PP];   // 17.4 KB
    const int tid = threadIdx.x;
    const int cg = tid & 15;
    const int rg = tid >> 4;
    const int rbase = blockIdx.x * 64;

    float acc[4][4];
    #pragma unroll
    for (int i = 0; i < 4; i++)
        #pragma unroll
        for (int j = 0; j < 4; j++) acc[i][j] = 0.0f;

    #pragma unroll
    for (int kc = 0; kc < FEAT; kc += 64) {
        #pragma unroll
        for (int s = 0; s < 4; s++) {
            int t = tid + s * 256;
            int r = t >> 4, k4 = t & 15;
            int gr = rbase + r;
            if (gr >= N_NODES) gr = N_NODES - 1;
            *(float4*)&Xs[r * PP + k4 * 4] =
                *(const float4*)&X[(size_t)gr * FEAT + kc + k4 * 4];
        }
        #pragma unroll
        for (int s = 0; s < 16; s++) {
            int t = tid + s * 256;
            int k = t >> 6, j = t & 63;
            Wt[j * PP + k] = W[(kc + k) * HID + j];
        }
        __syncthreads();

        #pragma unroll 4
        for (int k0 = 0; k0 < 64; k0 += 4) {
            float4 xv[4];
            #pragma unroll
            for (int i = 0; i < 4; i++)
                xv[i] = *(const float4*)&Xs[(rg + 16 * i) * PP + k0];
            #pragma unroll
            for (int j = 0; j < 4; j++) {
                float4 wv = *(const float4*)&Wt[(cg + 16 * j) * PP + k0];
                #pragma unroll
                for (int i = 0; i < 4; i++) {
                    acc[i][j] += xv[i].x * wv.x; acc[i][j] += xv[i].y * wv.y;
                    acc[i][j] += xv[i].z * wv.z; acc[i][j] += xv[i].w * wv.w;
                }
            }
        }
        __syncthreads();
    }

    #pragma unroll
    for (int i = 0; i < 4; i++) {
        int r = rbase + rg + 16 * i;
        if (r < N_NODES) {
            float d2 = 1.0f / g_deg[r];
            #pragma unroll
            for (int j = 0; j < 4; j++) {
                int c = cg + 16 * j;
                g_h1h[(size_t)r * HID + c] = __float2half_rn(acc[i][j]);
                g_acc1[(size_t)r * HID + c] = acc[i][j] * d2;
            }
        }
    }
}

// ---------------- bnprep: layer1 BN scale/shift from g_sum ------------------
__global__ void bnprep_kernel(const float* __restrict__ gamma, const float* __restrict__ beta) {
    int j = threadIdx.x;   // 64 threads
    float m   = g_sum[j] * (1.0f / N_NODES);
    float var = g_sum[HID + j] * (1.0f / N_NODES) - m * m;
    float inv = rsqrtf(var + EPS);
    float sc = inv * gamma[j];
    g_bnsc[j] = sc;
    g_bnsh[j] = beta[j] - m * sc;
}

// ---------------- gemm2: h2 = relu(bn(acc1)) @ W2 ; acc2 = h2 / deg ---------
__global__ void gemm2_kernel(const float* __restrict__ W) {
    __shared__ float Xs[64 * PP];
    __shared__ float Wt[64 * PP];
    const int tid = threadIdx.x;
    const int cg = tid & 15;
    const int rg = tid >> 4;
    const int rbase = blockIdx.x * 64;

    // stage X: BN+ReLU fused
    #pragma unroll
    for (int s = 0; s < 4; s++) {
        int t = tid + s * 256;
        int r = t >> 4, k4 = t & 15;
        int gr = rbase + r;
        if (gr >= N_NODES) gr = N_NODES - 1;
        float4 v = *(const float4*)&g_acc1[(size_t)gr * HID + k4 * 4];
        float4 sc = *(const float4*)&g_bnsc[k4 * 4];
        float4 sh = *(const float4*)&g_bnsh[k4 * 4];
        v.x = fmaxf(fmaf(v.x, sc.x, sh.x), 0.f);
        v.y = fmaxf(fmaf(v.y, sc.y, sh.y), 0.f);
        v.z = fmaxf(fmaf(v.z, sc.z, sh.z), 0.f);
        v.w = fmaxf(fmaf(v.w, sc.w, sh.w), 0.f);
        *(float4*)&Xs[r * PP + k4 * 4] = v;
    }
    #pragma unroll
    for (int s = 0; s < 16; s++) {
        int t = tid + s * 256;
        int k = t >> 6, j = t & 63;
        Wt[j * PP + k] = W[k * HID + j];
    }
    __syncthreads();

    float acc[4][4];
    #pragma unroll
    for (int i = 0; i < 4; i++)
        #pragma unroll
        for (int j = 0; j < 4; j++) acc[i][j] = 0.0f;

    #pragma unroll 4
    for (int k0 = 0; k0 < HID; k0 += 4) {
        float4 xv[4];
        #pragma unroll
        for (int i = 0; i < 4; i++)
            xv[i] = *(const float4*)&Xs[(rg + 16 * i) * PP + k0];
        #pragma unroll
        for (int j = 0; j < 4; j++) {
            float4 wv = *(const float4*)&Wt[(cg + 16 * j) * PP + k0];
            #pragma unroll
            for (int i = 0; i < 4; i++) {
                acc[i][j] += xv[i].x * wv.x; acc[i][j] += xv[i].y * wv.y;
                acc[i][j] += xv[i].z * wv.z; acc[i][j] += xv[i].w * wv.w;
            }
        }
    }

    #pragma unroll
    for (int i = 0; i < 4; i++) {
        int r = rbase + rg + 16 * i;
        if (r < N_NODES) {
            float d2 = 1.0f / g_deg[r];
            #pragma unroll
            for (int j = 0; j < 4; j++) {
                int c = cg + 16 * j;
                g_h2h[(size_t)r * HID + c] = __float2half_rn(acc[i][j]);
                g_acc2[(size_t)r * HID + c] = acc[i][j] * d2;
            }
        }
    }
}

// ---------------- gather (fp16 messages, int2 records, 4-wide MLP) ----------
// 256 thr = 16 nodes x 16 slices; slice p covers cols p*4..p*4+3 (8 B loads).
__global__ void gather_kernel(int layer) {
    const __half* h = layer ? g_h2h : g_h1h;
    float* acc      = layer ? g_acc2 : g_acc1;
    __shared__ float ssum[16 * HID];
    __shared__ float ssq[16 * HID];
    int ng = threadIdx.x >> 4;
    int p = threadIdx.x & 15;
    int node = blockIdx.x * 16 + ng;
    float* dst = acc + (size_t)node * HID + p * 4;
    float4 a = *(float4*)dst;   // self-loop term from gemm (fp32)
    int i = g_start[node];
    int t = g_start[node + 1];
    for (; i + 3 < t; i += 4) {
        int2 e0 = g_edge[i],     e1 = g_edge[i + 1];
        int2 e2 = g_edge[i + 2], e3 = g_edge[i + 3];
        __half2 a0 = *(const __half2*)&h[(size_t)e0.x * HID + p * 4];
        __half2 b0 = *(const __half2*)&h[(size_t)e0.x * HID + p * 4 + 2];
        __half2 a1 = *(const __half2*)&h[(size_t)e1.x * HID + p * 4];
        __half2 b1 = *(const __half2*)&h[(size_t)e1.x * HID + p * 4 + 2];
        __half2 a2 = *(const __half2*)&h[(size_t)e2.x * HID + p * 4];
        __half2 b2 = *(const __half2*)&h[(size_t)e2.x * HID + p * 4 + 2];
        __half2 a3 = *(const __half2*)&h[(size_t)e3.x * HID + p * 4];
        __half2 b3 = *(const __half2*)&h[(size_t)e3.x * HID + p * 4 + 2];
        float n0 = __int_as_float(e0.y), n1 = __int_as_float(e1.y);
        float n2 = __int_as_float(e2.y), n3 = __int_as_float(e3.y);
        float2 f;
        f = __half22float2(a0); a.x += f.x * n0; a.y += f.y * n0;
        f = __half22float2(b0); a.z += f.x * n0; a.w += f.y * n0;
        f = __half22float2(a1); a.x += f.x * n1; a.y += f.y * n1;
        f = __half22float2(b1); a.z += f.x * n1; a.w += f.y * n1;
        f = __half22float2(a2); a.x += f.x * n2; a.y += f.y * n2;
        f = __half22float2(b2); a.z += f.x * n2; a.w += f.y * n2;
        f = __half22float2(a3); a.x += f.x * n3; a.y += f.y * n3;
        f = __half22float2(b3); a.z += f.x * n3; a.w += f.y * n3;
    }
    for (; i < t; i++) {
        int2 e0 = g_edge[i];
        float n0 = __int_as_float(e0.y);
        __half2 u0 = *(const __half2*)&h[(size_t)e0.x * HID + p * 4];
        __half2 u1 = *(const __half2*)&h[(size_t)e0.x * HID + p * 4 + 2];
        float2 f0 = __half22float2(u0), f1 = __half22float2(u1);
        a.x += f0.x * n0; a.y += f0.y * n0; a.z += f1.x * n0; a.w += f1.y * n0;
    }
    *(float4*)dst = a;
    // fused BN stats
    ssum[ng * HID + p * 4 + 0] = a.x; ssq[ng * HID + p * 4 + 0] = a.x * a.x;
    ssum[ng * HID + p * 4 + 1] = a.y; ssq[ng * HID + p * 4 + 1] = a.y * a.y;
    ssum[ng * HID + p * 4 + 2] = a.z; ssq[ng * HID + p * 4 + 2] = a.z * a.z;
    ssum[ng * HID + p * 4 + 3] = a.w; ssq[ng * HID + p * 4 + 3] = a.w * a.w;
    __syncthreads();
    float* sums = g_sum + layer * 2 * HID;
    if (threadIdx.x < 64) {
        int j = threadIdx.x;
        float s = 0.f;
        #pragma unroll
        for (int r = 0; r < 16; r++) s += ssum[r * HID + j];
        atomicAdd(&sums[j], s);
    } else if (threadIdx.x < 128) {
        int j = threadIdx.x - 64;
        float q = 0.f;
        #pragma unroll
        for (int r = 0; r < 16; r++) q += ssq[r * HID + j];
        atomicAdd(&sums[HID + j], q);
    }
}

// ---------------- BN+ReLU layer2 fused with segment-max ---------------------
__global__ void bnrelu2max_kernel(const int* __restrict__ batch,
                                  const float* __restrict__ gamma,
                                  const float* __restrict__ beta) {
    int j = threadIdx.x & 63;
    int g = threadIdx.x >> 6;
    int rbase = (blockIdx.x * 4 + g) * 8;
    if (rbase >= N_NODES) return;
    float m   = g_sum[2 * HID + j] * (1.0f / N_NODES);
    float var = g_sum[3 * HID + j] * (1.0f / N_NODES) - m * m;
    float inv = rsqrtf(var + EPS);
    float gj = gamma[j], bj = beta[j];
    int cur = -1;
    float mx = 0.f;
    #pragma unroll
    for (int k = 0; k < 8; k++) {
        int r = rbase + k;
        if (r >= N_NODES) break;
        int b = batch[r];
        float v = fmaxf((g_acc2[(size_t)r * HID + j] - m) * inv * gj + bj, 0.f);
        if (b != cur) {
            if (cur >= 0 && mx > 0.f) atomicMax(&g_gx[cur * HID + j], __float_as_uint(mx));
            cur = b; mx = v;
        } else {
            mx = fmaxf(mx, v);
        }
    }
    if (cur >= 0 && mx > 0.f) atomicMax(&g_gx[cur * HID + j], __float_as_uint(mx));
}

// ---------------- head: speed enc + route enc + MLP (one block, 64 thr) -----
__global__ void head_kernel(const float* __restrict__ speed, const float* __restrict__ route,
                            const float* __restrict__ sw, const float* __restrict__ sb,
                            const float* __restrict__ sg, const float* __restrict__ sbe,
                            const float* __restrict__ cw, const float* __restrict__ cb,
                            const float* __restrict__ rg, const float* __restrict__ rbe,
                            const float* __restrict__ rw, const float* __restrict__ rb,
                            const float* __restrict__ ow1, const float* __restrict__ ob1,
                            const float* __restrict__ og, const float* __restrict__ obe,
                            const float* __restrict__ ow2, const float* __restrict__ ob2,
                            float* __restrict__ out) {
    int b = threadIdx.x;  // 64 threads
    __shared__ float s_v[NB][4];
    __shared__ float s_rc[NB][10];
    __shared__ float s_o1[NB][16];
    __shared__ float s_m[16], s_i[16];

    float sp = speed[b];
    #pragma unroll
    for (int j = 0; j < 4; j++) s_v[b][j] = sp * sw[j] + sb[j];

    const float* rt = route + b * 20;
    #pragma unroll
    for (int t = 0; t < 10; t++) {
        float a = cb[0];
        #pragma unroll
        for (int k = 0; k < 3; k++) {
            int tau = t + k - 1;
            if (tau >= 0 && tau < 10) {
                a += rt[tau * 2 + 0] * cw[k];
                a += rt[tau * 2 + 1] * cw[3 + k];
            }
        }
        s_rc[b][t] = a;
    }
    __syncthreads();

    if (b < 4) {
        float s = 0.f, q = 0.f;
        for (int i = 0; i < NB; i++) { float v = s_v[i][b]; s += v; q += v * v; }
        float m = s / NB, var = q / NB - m * m;
        s_m[b] = m; s_i[b] = rsqrtf(var + EPS);
    }
    if (b == 8) {
        float s = 0.f, q = 0.f;
        for (int i = 0; i < NB; i++)
            for (int t = 0; t < 10; t++) { float v = s_rc[i][t]; s += v; q += v * v; }
        float m = s / 640.f, var = q / 640.f - m * m;
        s_m[8] = m; s_i[8] = rsqrtf(var + EPS);
    }
    __syncthreads();

    float vj[4];
    #pragma unroll
    for (int j = 0; j < 4; j++)
        vj[j] = fmaxf((s_v[b][j] - s_m[j]) * s_i[j] * sg[j] + sbe[j], 0.f);

    float rcn[10];
    #pragma unroll
    for (int t = 0; t < 10; t++)
        rcn[t] = fmaxf((s_rc[b][t] - s_m[8]) * s_i[8] * rg[0] + rbe[0], 0.f);

    float rj[4];
    #pragma unroll
    for (int j = 0; j < 4; j++) {
        float a = rb[j];
        #pragma unroll
        for (int t = 0; t < 10; t++) a += rcn[t] * rw[t * 4 + j];
        rj[j] = a;
    }

    #pragma unroll
    for (int j = 0; j < 16; j++) {
        float a = ob1[j];
        for (int k = 0; k < HID; k++)
            a += __uint_as_float(g_gx[b * HID + k]) * ow1[k * 16 + j];
        #pragma unroll
        for (int k = 0; k < 4; k++) a += vj[k] * ow1[(HID + k) * 16 + j];
        #pragma unroll
        for (int k = 0; k < 4; k++) a += rj[k] * ow1[(HID + 4 + k) * 16 + j];
        s_o1[b][j] = a;
    }
    __syncthreads();
    if (b < 16) {
        float s = 0.f, q = 0.f;
        for (int i = 0; i < NB; i++) { float v = s_o1[i][b]; s += v; q += v * v; }
        float m = s / NB, var = q / NB - m * m;
        s_m[b] = m; s_i[b] = rsqrtf(var + EPS);
    }
    __syncthreads();
    float on[16];
    #pragma unroll
    for (int j = 0; j < 16; j++)
        on[j] = fmaxf((s_o1[b][j] - s_m[j]) * s_i[j] * og[j] + obe[j], 0.f);
    #pragma unroll
    for (int a = 0; a < 5; a++) {
        float o = ob2[a];
        #pragma unroll
        for (int j = 0; j < 16; j++) o += on[j] * ow2[j * 5 + a];
        out[b * 5 + a] = o;
    }
}

// ---------------------------------------------------------------------------
extern "C" void kernel_launch(void* const* d_in, const int* in_sizes, int n_in,
                              void* d_out, int out_size) {
    const float* x    = (const float*)d_in[0];
    const int*   ei   = (const int*)d_in[1];
    const float* ew   = (const float*)d_in[2];
    const int*   bidx = (const int*)d_in[3];
    const float* speed = (const float*)d_in[4];
    const float* route = (const float*)d_in[5];
    const float* W1 = (const float*)d_in[6];
    const float* g1 = (const float*)d_in[8];
    const float* be1 = (const float*)d_in[9];
    const float* W2 = (const float*)d_in[10];
    const float* g2 = (const float*)d_in[12];
    const float* be2 = (const float*)d_in[13];
    const float* sw  = (const float*)d_in[14];
    const float* sb  = (const float*)d_in[15];
    const float* sg  = (const float*)d_in[16];
    const float* sbe = (const float*)d_in[17];
    const float* cw  = (const float*)d_in[18];
    const float* cb  = (const float*)d_in[19];
    const float* rg  = (const float*)d_in[20];
    const float* rbe = (const float*)d_in[21];
    const float* rw  = (const float*)d_in[22];
    const float* rb  = (const float*)d_in[23];
    const float* ow1 = (const float*)d_in[24];
    const float* ob1 = (const float*)d_in[25];
    const float* og  = (const float*)d_in[26];
    const float* obe = (const float*)d_in[27];
    const float* ow2 = (const float*)d_in[28];
    const float* ob2 = (const float*)d_in[29];
    float* out = (float*)d_out;

    const int* row = ei;            // edge_index[0]
    const int* col = ei + N_EDGES;  // edge_index[1]

    init_kernel<<<(N_NODES + 255) / 256, 256>>>();
    deg_kernel<<<(N_EDGES + 255) / 256, 256>>>(col, ew);
    scan1_kernel<<<NBLK, 256>>>();
    scan2_kernel<<<1, 512>>>();
    scan3_kernel<<<NBLK, 256>>>();
    fill_kernel<<<(N_EDGES + 255) / 256, 256>>>(row, col, ew);

    gemm1_kernel<<<(N_NODES + 63) / 64, 256>>>(x, W1);
    gather_kernel<<<N_NODES / 16, 256>>>(0);
    bnprep_kernel<<<1, 64>>>(g1, be1);

    gemm2_kernel<<<(N_NODES + 63) / 64, 256>>>(W2);
    gather_kernel<<<N_NODES / 16, 256>>>(1);
    bnrelu2max_kernel<<<(N_NODES + 31) / 32, 256>>>(bidx, g2, be2);

    head_kernel<<<1, 64>>>(speed, route, sw, sb, sg, sbe, cw, cb, rg, rbe,
                           rw, rb, ow1, ob1, og, obe, ow2, ob2, out);
}

// round 14
// speedup vs baseline: 2.3566x; 1.0461x over previous
#include <cuda_runtime.h>
#include <cuda_bf16.h>
#include <cuda_fp16.h>

#define N_NODES 100000
#define N_EDGES 1600000
#define HID 64
#define FEAT 128
#define NB 64
#define EPS 1e-5f
#define NBLK 391   // ceil(N_NODES/256)

// ---------------- scratch (static device globals; no allocs) ----------------
__device__ float    g_deg[N_NODES];
__device__ __half   g_h1h[N_NODES * HID];   // fp16 messages, layer1
__device__ __half   g_h2h[N_NODES * HID];   // fp16 messages, layer2
__device__ float    g_acc1[N_NODES * HID];
__device__ float    g_acc2[N_NODES * HID];
__device__ float    g_sum[4 * HID];      // [sum1, sq1, sum2, sq2]
__device__ float    g_bnsc[HID];         // layer1 BN scale
__device__ float    g_bnsh[HID];         // layer1 BN shift
__device__ unsigned g_gx[NB * HID];      // segment-max (float bits, all >= 0)
// CSR build
__device__ int      g_cnt[N_NODES];
__device__ int      g_start[N_NODES + 1];
__device__ int      g_bsum[512];
__device__ int      g_cursor[N_NODES];
__device__ int2     g_edge[N_EDGES];     // interleaved {src row, norm bits}

// ---------------- init: deg=1, zero stats/gx/cnt/cursor ---------------------
__global__ void init_kernel() {
    int i = blockIdx.x * 256 + threadIdx.x;
    if (i < N_NODES) { g_deg[i] = 1.0f; g_cnt[i] = 0; g_cursor[i] = 0; }
    if (i < 4 * HID) g_sum[i] = 0.0f;
    if (i < NB * HID) g_gx[i] = 0u;
    if (i == 0) g_start[N_NODES] = N_EDGES;
}

// ---------------- degree: deg[c] += w ; hist: cnt[c]++ ----------------------
__global__ void deg_kernel(const int* __restrict__ col, const float* __restrict__ w) {
    int e = blockIdx.x * 256 + threadIdx.x;
    if (e < N_EDGES) {
        int c = col[e];
        atomicAdd(&g_deg[c], w[e]);
        atomicAdd(&g_cnt[c], 1);
    }
}

// ---------------- scan of g_cnt -> g_start (2 kernels) ----------------------
__global__ void scan1_kernel() {
    __shared__ int sm[256];
    int i = blockIdx.x * 256 + threadIdx.x;
    int v = (i < N_NODES) ? g_cnt[i] : 0;
    sm[threadIdx.x] = v;
    __syncthreads();
    #pragma unroll
    for (int d = 1; d < 256; d <<= 1) {
        int t = (threadIdx.x >= d) ? sm[threadIdx.x - d] : 0;
        __syncthreads();
        sm[threadIdx.x] += t;
        __syncthreads();
    }
    if (i < N_NODES) g_start[i] = sm[threadIdx.x] - v;   // exclusive within block
    if (threadIdx.x == 255) g_bsum[blockIdx.x] = sm[255];  // raw block total
}
// scan3: add prefix of block totals (computed in-block) to each element
__global__ void scan3_kernel() {
    __shared__ int red[256];
    int tid = threadIdx.x;
    int s = 0;
    for (int k = tid; k < blockIdx.x; k += 256) s += g_bsum[k];
    red[tid] = s;
    __syncthreads();
    #pragma unroll
    for (int d = 128; d > 0; d >>= 1) {
        if (tid < d) red[tid] += red[tid + d];
        __syncthreads();
    }
    int off = red[0];
    int i = blockIdx.x * 256 + tid;
    if (i < N_NODES) g_start[i] += off;
}

// ---------------- fill CSR: interleaved (row, norm) record ------------------
__global__ void fill_kernel(const int* __restrict__ row, const int* __restrict__ col,
                            const float* __restrict__ w) {
    int e = blockIdx.x * 256 + threadIdx.x;
    if (e >= N_EDGES) return;
    int c = col[e];
    int r = row[e];
    int p = atomicAdd(&g_cursor[c], 1);
    float nm = w[e] * rsqrtf(g_deg[r] * g_deg[c]);
    g_edge[g_start[c] + p] = make_int2(r, __float_as_int(nm));
}

// ---------------- gemm1: h1 = x @ W1 (fp16 only) ----------------------------
// 64 rows x 64 cols per block, 256 thr = 16 rg x 16 cg, 4x4 per thread.
#define PP 68
__global__ void gemm1_kernel(const float* __restrict__ X, const float* __restrict__ W) {
    __shared__ float Xs[64 * PP];   // 17.4 KB
    __shared__ float Wt[64 * PP];   // 17.4 KB
    const int tid = threadIdx.x;
    const int cg = tid & 15;
    const int rg = tid >> 4;
    const int rbase = blockIdx.x * 64;

    float acc[4][4];
    #pragma unroll
    for (int i = 0; i < 4; i++)
        #pragma unroll
        for (int j = 0; j < 4; j++) acc[i][j] = 0.0f;

    #pragma unroll
    for (int kc = 0; kc < FEAT; kc += 64) {
        #pragma unroll
        for (int s = 0; s < 4; s++) {
            int t = tid + s * 256;
            int r = t >> 4, k4 = t & 15;
            int gr = rbase + r;
            if (gr >= N_NODES) gr = N_NODES - 1;
            *(float4*)&Xs[r * PP + k4 * 4] =
                *(const float4*)&X[(size_t)gr * FEAT + kc + k4 * 4];
        }
        #pragma unroll
        for (int s = 0; s < 16; s++) {
            int t = tid + s * 256;
            int k = t >> 6, j = t & 63;
            Wt[j * PP + k] = W[(kc + k) * HID + j];
        }
        __syncthreads();

        #pragma unroll 4
        for (int k0 = 0; k0 < 64; k0 += 4) {
            float4 xv[4];
            #pragma unroll
            for (int i = 0; i < 4; i++)
                xv[i] = *(const float4*)&Xs[(rg + 16 * i) * PP + k0];
            #pragma unroll
            for (int j = 0; j < 4; j++) {
                float4 wv = *(const float4*)&Wt[(cg + 16 * j) * PP + k0];
                #pragma unroll
                for (int i = 0; i < 4; i++) {
                    acc[i][j] += xv[i].x * wv.x; acc[i][j] += xv[i].y * wv.y;
                    acc[i][j] += xv[i].z * wv.z; acc[i][j] += xv[i].w * wv.w;
                }
            }
        }
        __syncthreads();
    }

    #pragma unroll
    for (int i = 0; i < 4; i++) {
        int r = rbase + rg + 16 * i;
        if (r < N_NODES) {
            #pragma unroll
            for (int j = 0; j < 4; j++)
                g_h1h[(size_t)r * HID + cg + 16 * j] = __float2half_rn(acc[i][j]);
        }
    }
}

// ---------------- bnprep: layer1 BN scale/shift from g_sum ------------------
__global__ void bnprep_kernel(const float* __restrict__ gamma, const float* __restrict__ beta) {
    int j = threadIdx.x;   // 64 threads
    float m   = g_sum[j] * (1.0f / N_NODES);
    float var = g_sum[HID + j] * (1.0f / N_NODES) - m * m;
    float inv = rsqrtf(var + EPS);
    float sc = inv * gamma[j];
    g_bnsc[j] = sc;
    g_bnsh[j] = beta[j] - m * sc;
}

// ---------------- gemm2: h2 = relu(bn(acc1)) @ W2 (fp16 only) ---------------
__global__ void gemm2_kernel(const float* __restrict__ W) {
    __shared__ float Xs[64 * PP];
    __shared__ float Wt[64 * PP];
    const int tid = threadIdx.x;
    const int cg = tid & 15;
    const int rg = tid >> 4;
    const int rbase = blockIdx.x * 64;

    // stage X: BN+ReLU fused
    #pragma unroll
    for (int s = 0; s < 4; s++) {
        int t = tid + s * 256;
        int r = t >> 4, k4 = t & 15;
        int gr = rbase + r;
        if (gr >= N_NODES) gr = N_NODES - 1;
        float4 v = *(const float4*)&g_acc1[(size_t)gr * HID + k4 * 4];
        float4 sc = *(const float4*)&g_bnsc[k4 * 4];
        float4 sh = *(const float4*)&g_bnsh[k4 * 4];
        v.x = fmaxf(fmaf(v.x, sc.x, sh.x), 0.f);
        v.y = fmaxf(fmaf(v.y, sc.y, sh.y), 0.f);
        v.z = fmaxf(fmaf(v.z, sc.z, sh.z), 0.f);
        v.w = fmaxf(fmaf(v.w, sc.w, sh.w), 0.f);
        *(float4*)&Xs[r * PP + k4 * 4] = v;
    }
    #pragma unroll
    for (int s = 0; s < 16; s++) {
        int t = tid + s * 256;
        int k = t >> 6, j = t & 63;
        Wt[j * PP + k] = W[k * HID + j];
    }
    __syncthreads();

    float acc[4][4];
    #pragma unroll
    for (int i = 0; i < 4; i++)
        #pragma unroll
        for (int j = 0; j < 4; j++) acc[i][j] = 0.0f;

    #pragma unroll 4
    for (int k0 = 0; k0 < HID; k0 += 4) {
        float4 xv[4];
        #pragma unroll
        for (int i = 0; i < 4; i++)
            xv[i] = *(const float4*)&Xs[(rg + 16 * i) * PP + k0];
        #pragma unroll
        for (int j = 0; j < 4; j++) {
            float4 wv = *(const float4*)&Wt[(cg + 16 * j) * PP + k0];
            #pragma unroll
            for (int i = 0; i < 4; i++) {
                acc[i][j] += xv[i].x * wv.x; acc[i][j] += xv[i].y * wv.y;
                acc[i][j] += xv[i].z * wv.z; acc[i][j] += xv[i].w * wv.w;
            }
        }
    }

    #pragma unroll
    for (int i = 0; i < 4; i++) {
        int r = rbase + rg + 16 * i;
        if (r < N_NODES) {
            #pragma unroll
            for (int j = 0; j < 4; j++)
                g_h2h[(size_t)r * HID + cg + 16 * j] = __float2half_rn(acc[i][j]);
        }
    }
}

// ---------------- gather: self-loop (h/deg) + messages + fused BN stats -----
// 256 thr = 16 nodes x 16 slices; slice p covers cols p*4..p*4+3 (8 B loads).
__global__ void gather_kernel(int layer) {
    const __half* h = layer ? g_h2h : g_h1h;
    float* acc      = layer ? g_acc2 : g_acc1;
    __shared__ float ssum[16 * HID];
    __shared__ float ssq[16 * HID];
    int ng = threadIdx.x >> 4;
    int p = threadIdx.x & 15;
    int node = blockIdx.x * 16 + ng;
    // self-loop term: h[node] / deg[node]
    float invd = 1.0f / g_deg[node];
    __half2 s0 = *(const __half2*)&h[(size_t)node * HID + p * 4];
    __half2 s1 = *(const __half2*)&h[(size_t)node * HID + p * 4 + 2];
    float2 sf0 = __half22float2(s0), sf1 = __half22float2(s1);
    float4 a = make_float4(sf0.x * invd, sf0.y * invd, sf1.x * invd, sf1.y * invd);
    int i = g_start[node];
    int t = g_start[node + 1];
    for (; i + 3 < t; i += 4) {
        int2 e0 = g_edge[i],     e1 = g_edge[i + 1];
        int2 e2 = g_edge[i + 2], e3 = g_edge[i + 3];
        __half2 a0 = *(const __half2*)&h[(size_t)e0.x * HID + p * 4];
        __half2 b0 = *(const __half2*)&h[(size_t)e0.x * HID + p * 4 + 2];
        __half2 a1 = *(const __half2*)&h[(size_t)e1.x * HID + p * 4];
        __half2 b1 = *(const __half2*)&h[(size_t)e1.x * HID + p * 4 + 2];
        __half2 a2 = *(const __half2*)&h[(size_t)e2.x * HID + p * 4];
        __half2 b2 = *(const __half2*)&h[(size_t)e2.x * HID + p * 4 + 2];
        __half2 a3 = *(const __half2*)&h[(size_t)e3.x * HID + p * 4];
        __half2 b3 = *(const __half2*)&h[(size_t)e3.x * HID + p * 4 + 2];
        float n0 = __int_as_float(e0.y), n1 = __int_as_float(e1.y);
        float n2 = __int_as_float(e2.y), n3 = __int_as_float(e3.y);
        float2 f;
        f = __half22float2(a0); a.x += f.x * n0; a.y += f.y * n0;
        f = __half22float2(b0); a.z += f.x * n0; a.w += f.y * n0;
        f = __half22float2(a1); a.x += f.x * n1; a.y += f.y * n1;
        f = __half22float2(b1); a.z += f.x * n1; a.w += f.y * n1;
        f = __half22float2(a2); a.x += f.x * n2; a.y += f.y * n2;
        f = __half22float2(b2); a.z += f.x * n2; a.w += f.y * n2;
        f = __half22float2(a3); a.x += f.x * n3; a.y += f.y * n3;
        f = __half22float2(b3); a.z += f.x * n3; a.w += f.y * n3;
    }
    for (; i < t; i++) {
        int2 e0 = g_edge[i];
        float n0 = __int_as_float(e0.y);
        __half2 u0 = *(const __half2*)&h[(size_t)e0.x * HID + p * 4];
        __half2 u1 = *(const __half2*)&h[(size_t)e0.x * HID + p * 4 + 2];
        float2 f0 = __half22float2(u0), f1 = __half22float2(u1);
        a.x += f0.x * n0; a.y += f0.y * n0; a.z += f1.x * n0; a.w += f1.y * n0;
    }
    *(float4*)(acc + (size_t)node * HID + p * 4) = a;
    // fused BN stats
    ssum[ng * HID + p * 4 + 0] = a.x; ssq[ng * HID + p * 4 + 0] = a.x * a.x;
    ssum[ng * HID + p * 4 + 1] = a.y; ssq[ng * HID + p * 4 + 1] = a.y * a.y;
    ssum[ng * HID + p * 4 + 2] = a.z; ssq[ng * HID + p * 4 + 2] = a.z * a.z;
    ssum[ng * HID + p * 4 + 3] = a.w; ssq[ng * HID + p * 4 + 3] = a.w * a.w;
    __syncthreads();
    float* sums = g_sum + layer * 2 * HID;
    if (threadIdx.x < 64) {
        int j = threadIdx.x;
        float s = 0.f;
        #pragma unroll
        for (int r = 0; r < 16; r++) s += ssum[r * HID + j];
        atomicAdd(&sums[j], s);
    } else if (threadIdx.x < 128) {
        int j = threadIdx.x - 64;
        float q = 0.f;
        #pragma unroll
        for (int r = 0; r < 16; r++) q += ssq[r * HID + j];
        atomicAdd(&sums[HID + j], q);
    }
}

// ---------------- BN+ReLU layer2 fused with segment-max ---------------------
__global__ void bnrelu2max_kernel(const int* __restrict__ batch,
                                  const float* __restrict__ gamma,
                                  const float* __restrict__ beta) {
    int j = threadIdx.x & 63;
    int g = threadIdx.x >> 6;
    int rbase = (blockIdx.x * 4 + g) * 8;
    if (rbase >= N_NODES) return;
    float m   = g_sum[2 * HID + j] * (1.0f / N_NODES);
    float var = g_sum[3 * HID + j] * (1.0f / N_NODES) - m * m;
    float inv = rsqrtf(var + EPS);
    float gj = gamma[j], bj = beta[j];
    int cur = -1;
    float mx = 0.f;
    #pragma unroll
    for (int k = 0; k < 8; k++) {
        int r = rbase + k;
        if (r >= N_NODES) break;
        int b = batch[r];
        float v = fmaxf((g_acc2[(size_t)r * HID + j] - m) * inv * gj + bj, 0.f);
        if (b != cur) {
            if (cur >= 0 && mx > 0.f) atomicMax(&g_gx[cur * HID + j], __float_as_uint(mx));
            cur = b; mx = v;
        } else {
            mx = fmaxf(mx, v);
        }
    }
    if (cur >= 0 && mx > 0.f) atomicMax(&g_gx[cur * HID + j], __float_as_uint(mx));
}

// ---------------- head: speed enc + route enc + MLP (one block, 64 thr) -----
__global__ void head_kernel(const float* __restrict__ speed, const float* __restrict__ route,
                            const float* __restrict__ sw, const float* __restrict__ sb,
                            const float* __restrict__ sg, const float* __restrict__ sbe,
                            const float* __restrict__ cw, const float* __restrict__ cb,
                            const float* __restrict__ rg, const float* __restrict__ rbe,
                            const float* __restrict__ rw, const float* __restrict__ rb,
                            const float* __restrict__ ow1, const float* __restrict__ ob1,
                            const float* __restrict__ og, const float* __restrict__ obe,
                            const float* __restrict__ ow2, const float* __restrict__ ob2,
                            float* __restrict__ out) {
    int b = threadIdx.x;  // 64 threads
    __shared__ float s_v[NB][4];
    __shared__ float s_rc[NB][10];
    __shared__ float s_o1[NB][16];
    __shared__ float s_m[16], s_i[16];

    float sp = speed[b];
    #pragma unroll
    for (int j = 0; j < 4; j++) s_v[b][j] = sp * sw[j] + sb[j];

    const float* rt = route + b * 20;
    #pragma unroll
    for (int t = 0; t < 10; t++) {
        float a = cb[0];
        #pragma unroll
        for (int k = 0; k < 3; k++) {
            int tau = t + k - 1;
            if (tau >= 0 && tau < 10) {
                a += rt[tau * 2 + 0] * cw[k];
                a += rt[tau * 2 + 1] * cw[3 + k];
            }
        }
        s_rc[b][t] = a;
    }
    __syncthreads();

    if (b < 4) {
        float s = 0.f, q = 0.f;
        for (int i = 0; i < NB; i++) { float v = s_v[i][b]; s += v; q += v * v; }
        float m = s / NB, var = q / NB - m * m;
        s_m[b] = m; s_i[b] = rsqrtf(var + EPS);
    }
    if (b == 8) {
        float s = 0.f, q = 0.f;
        for (int i = 0; i < NB; i++)
            for (int t = 0; t < 10; t++) { float v = s_rc[i][t]; s += v; q += v * v; }
        float m = s / 640.f, var = q / 640.f - m * m;
        s_m[8] = m; s_i[8] = rsqrtf(var + EPS);
    }
    __syncthreads();

    float vj[4];
    #pragma unroll
    for (int j = 0; j < 4; j++)
        vj[j] = fmaxf((s_v[b][j] - s_m[j]) * s_i[j] * sg[j] + sbe[j], 0.f);

    float rcn[10];
    #pragma unroll
    for (int t = 0; t < 10; t++)
        rcn[t] = fmaxf((s_rc[b][t] - s_m[8]) * s_i[8] * rg[0] + rbe[0], 0.f);

    float rj[4];
    #pragma unroll
    for (int j = 0; j < 4; j++) {
        float a = rb[j];
        #pragma unroll
        for (int t = 0; t < 10; t++) a += rcn[t] * rw[t * 4 + j];
        rj[j] = a;
    }

    #pragma unroll
    for (int j = 0; j < 16; j++) {
        float a = ob1[j];
        for (int k = 0; k < HID; k++)
            a += __uint_as_float(g_gx[b * HID + k]) * ow1[k * 16 + j];
        #pragma unroll
        for (int k = 0; k < 4; k++) a += vj[k] * ow1[(HID + k) * 16 + j];
        #pragma unroll
        for (int k = 0; k < 4; k++) a += rj[k] * ow1[(HID + 4 + k) * 16 + j];
        s_o1[b][j] = a;
    }
    __syncthreads();
    if (b < 16) {
        float s = 0.f, q = 0.f;
        for (int i = 0; i < NB; i++) { float v = s_o1[i][b]; s += v; q += v * v; }
        float m = s / NB, var = q / NB - m * m;
        s_m[b] = m; s_i[b] = rsqrtf(var + EPS);
    }
    __syncthreads();
    float on[16];
    #pragma unroll
    for (int j = 0; j < 16; j++)
        on[j] = fmaxf((s_o1[b][j] - s_m[j]) * s_i[j] * og[j] + obe[j], 0.f);
    #pragma unroll
    for (int a = 0; a < 5; a++) {
        float o = ob2[a];
        #pragma unroll
        for (int j = 0; j < 16; j++) o += on[j] * ow2[j * 5 + a];
        out[b * 5 + a] = o;
    }
}

// ---------------------------------------------------------------------------
extern "C" void kernel_launch(void* const* d_in, const int* in_sizes, int n_in,
                              void* d_out, int out_size) {
    const float* x    = (const float*)d_in[0];
    const int*   ei   = (const int*)d_in[1];
    const float* ew   = (const float*)d_in[2];
    const int*   bidx = (const int*)d_in[3];
    const float* speed = (const float*)d_in[4];
    const float* route = (const float*)d_in[5];
    const float* W1 = (const float*)d_in[6];
    const float* g1 = (const float*)d_in[8];
    const float* be1 = (const float*)d_in[9];
    const float* W2 = (const float*)d_in[10];
    const float* g2 = (const float*)d_in[12];
    const float* be2 = (const float*)d_in[13];
    const float* sw  = (const float*)d_in[14];
    const float* sb  = (const float*)d_in[15];
    const float* sg  = (const float*)d_in[16];
    const float* sbe = (const float*)d_in[17];
    const float* cw  = (const float*)d_in[18];
    const float* cb  = (const float*)d_in[19];
    const float* rg  = (const float*)d_in[20];
    const float* rbe = (const float*)d_in[21];
    const float* rw  = (const float*)d_in[22];
    const float* rb  = (const float*)d_in[23];
    const float* ow1 = (const float*)d_in[24];
    const float* ob1 = (const float*)d_in[25];
    const float* og  = (const float*)d_in[26];
    const float* obe = (const float*)d_in[27];
    const float* ow2 = (const float*)d_in[28];
    const float* ob2 = (const float*)d_in[29];
    float* out = (float*)d_out;

    const int* row = ei;            // edge_index[0]
    const int* col = ei + N_EDGES;  // edge_index[1]

    init_kernel<<<(N_NODES + 255) / 256, 256>>>();
    deg_kernel<<<(N_EDGES + 255) / 256, 256>>>(col, ew);
    scan1_kernel<<<NBLK, 256>>>();
    scan3_kernel<<<NBLK, 256>>>();
    fill_kernel<<<(N_EDGES + 255) / 256, 256>>>(row, col, ew);

    gemm1_kernel<<<(N_NODES + 63) / 64, 256>>>(x, W1);
    gather_kernel<<<N_NODES / 16, 256>>>(0);
    bnprep_kernel<<<1, 64>>>(g1, be1);

    gemm2_kernel<<<(N_NODES + 63) / 64, 256>>>(W2);
    gather_kernel<<<N_NODES / 16, 256>>>(1);
    bnrelu2max_kernel<<<(N_NODES + 31) / 32, 256>>>(bidx, g2, be2);

    head_kernel<<<1, 64>>>(speed, route, sw, sb, sg, sbe, cw, cb, rg, rbe,
                           rw, rb, ow1, ob1, og, obe, ow2, ob2, out);
}